// round 4
// baseline (speedup 1.0000x reference)
#include <cuda_runtime.h>
#include <math.h>

#define NNODE 1024
#define EPS_F 1e-6f

// ---- scratch layout (floats) ----
#define OFF_H     ((size_t)0)
#define OFF_T0A   (OFF_H    + 4194304)
#define OFF_T0B   (OFF_T0A  + 4194304)
#define OFF_MA    (OFF_T0B  + 4194304)
#define OFF_MB    (OFF_MA   + 4194304)
#define OFF_SUMA  (OFF_MB   + 4194304)
#define OFF_SUMB  (OFF_SUMA + 4194304)
#define OFF_CNTA  (OFF_SUMB + 4194304)
#define OFF_CNTB  (OFF_CNTA + 32768)
#define OFF_COMBA (OFF_CNTB + 32768)
#define OFF_COMBB (OFF_COMBA + 8388608)
#define OFF_GTA   (OFF_COMBB + 8388608)
#define OFF_UTA   (OFF_GTA  + 4194304)
#define OFF_GTB   (OFF_UTA  + 4194304)
#define OFF_UTB   (OFF_GTB  + 4194304)
#define OFF_HC    (OFF_UTB  + 4194304)
#define OFF_Q2    (OFF_HC   + 8388608)
#define OFF_K2    (OFF_Q2   + 4194304)
#define OFF_V2    (OFF_K2   + 1048576)
#define OFF_OH    (OFF_V2   + 1048576)
#define OFF_HNUM  (OFF_OH   + 4194304)
#define OFF_WQF   (OFF_HNUM + 4096)
#define OFF_BQF   (OFF_WQF  + 32768)
#define OFF_WKF   (OFF_BQF  + 128)
#define OFF_BKF   (OFF_WKF  + 32768)
#define OFF_WVF   (OFF_BKF  + 128)
#define OFF_BVF   (OFF_WVF  + 32768)
#define SCRATCH_FLOATS (OFF_BVF + 128)

__device__ float g_scratch[SCRATCH_FLOATS];

__device__ __forceinline__ float ftanh(float x) {
    float t = __expf(2.0f * x);
    return 1.0f - __fdividef(2.0f, t + 1.0f);
}

__device__ __forceinline__ void red4(float* p, float4 v) {
    asm volatile("red.global.v4.f32.add [%0], {%1,%2,%3,%4};"
        :: "l"(p), "f"(v.x), "f"(v.y), "f"(v.z), "f"(v.w) : "memory");
}

// ---------------- h_num ----------------
__global__ void k_hnum(const float* __restrict__ num, const float* __restrict__ W0,
                       const float* __restrict__ b0, const float* __restrict__ W1,
                       const float* __restrict__ b1, float* __restrict__ out) {
    __shared__ float xs[64];
    __shared__ float hid[256];
    int b = blockIdx.x, t = threadIdx.x;
    if (t < 64) xs[t] = num[b * 64 + t];
    __syncthreads();
    float a = b0[t];
    #pragma unroll 8
    for (int k = 0; k < 64; k++) a += xs[k] * W0[k * 256 + t];
    hid[t] = ftanh(a);
    __syncthreads();
    if (t < 128) {
        float a2 = b1[t];
        #pragma unroll 8
        for (int k = 0; k < 256; k++) a2 += hid[k] * W1[k * 128 + t];
        out[b * 128 + t] = ftanh(a2);
    }
}

// ---------------- node embed ----------------
__global__ void __launch_bounds__(128) k_embed(const float* __restrict__ nf,
        const float* __restrict__ Wn, const float* __restrict__ bn,
        const float* __restrict__ pos, float* __restrict__ h) {
    __shared__ float ws[4096];
    __shared__ float xs[256];
    int t = threadIdx.x;
    int rbase = blockIdx.x * 8;
    for (int i = t; i < 4096; i += 128) ws[i] = Wn[i];
    for (int i = t; i < 256; i += 128) xs[i] = nf[(size_t)rbase * 32 + i];
    __syncthreads();
    float bv = bn[t];
    #pragma unroll
    for (int r = 0; r < 8; r++) {
        float a = bv;
        #pragma unroll 8
        for (int k = 0; k < 32; k++) a += xs[r * 32 + k] * ws[k * 128 + t];
        int row = rbase + r;
        h[(size_t)row * 128 + t] = ftanh(a) + pos[(size_t)(row & 1023) * 128 + t];
    }
}

// ---------------- batched 128x128-tile GEMM, 8x8 micro-tile ----------------
struct Jobs {
    const float* X[4];
    const float* W[4];
    const float* B[4];
    float* Y[4];
};

__global__ void __launch_bounds__(256) gemm128(Jobs jobs, int ldx, int rpb,
        size_t bstride, const int* __restrict__ rowmap, int ldy, int K, int act) {
    const float* __restrict__ X = jobs.X[blockIdx.y];
    const float* __restrict__ W = jobs.W[blockIdx.y];
    const float* __restrict__ bias = jobs.B[blockIdx.y];
    float* __restrict__ Y = jobs.Y[blockIdx.y];
    __shared__ float Xs[16][132];
    __shared__ float Ws[16][128];
    __shared__ unsigned rowoff[128];
    int tid = threadIdx.x;
    int rbase = blockIdx.x * 128;
    if (tid < 128) {
        int r = rbase + tid;
        int bb = r / rpb;
        int n = r - bb * rpb;
        if (rowmap) n = rowmap[n];
        rowoff[tid] = (unsigned)((size_t)bb * bstride + (size_t)n * ldx);
    }
    __syncthreads();
    float acc[8][8] = {};
    int r0 = (tid >> 4) * 8, c0 = (tid & 15) * 8;
    for (int kb = 0; kb < K; kb += 16) {
        #pragma unroll
        for (int p = 0; p < 8; p++) {
            int idx = p * 256 + tid;
            int m = idx >> 4, k = idx & 15;
            Xs[k][m] = X[rowoff[m] + kb + k];
        }
        #pragma unroll
        for (int p = 0; p < 8; p++) {
            int idx = p * 256 + tid;
            int k = idx >> 7, col = idx & 127;
            Ws[k][col] = W[(size_t)(kb + k) * 128 + col];
        }
        __syncthreads();
        #pragma unroll
        for (int k = 0; k < 16; k++) {
            float4 a0 = *(const float4*)&Xs[k][r0];
            float4 a1 = *(const float4*)&Xs[k][r0 + 4];
            float4 b0 = *(const float4*)&Ws[k][c0];
            float4 b1 = *(const float4*)&Ws[k][c0 + 4];
            float av[8] = {a0.x, a0.y, a0.z, a0.w, a1.x, a1.y, a1.z, a1.w};
            float bv[8] = {b0.x, b0.y, b0.z, b0.w, b1.x, b1.y, b1.z, b1.w};
            #pragma unroll
            for (int i = 0; i < 8; i++)
                #pragma unroll
                for (int j = 0; j < 8; j++) acc[i][j] += av[i] * bv[j];
        }
        __syncthreads();
    }
    float bz[8];
    #pragma unroll
    for (int j = 0; j < 8; j++) bz[j] = bias[c0 + j];
    #pragma unroll
    for (int i = 0; i < 8; i++) {
        float o[8];
        #pragma unroll
        for (int j = 0; j < 8; j++) {
            o[j] = acc[i][j] + bz[j];
            if (act) o[j] = ftanh(o[j]);
        }
        size_t yoff = (size_t)(rbase + r0 + i) * ldy + c0;
        *(float4*)(Y + yoff)     = make_float4(o[0], o[1], o[2], o[3]);
        *(float4*)(Y + yoff + 4) = make_float4(o[4], o[5], o[6], o[7]);
    }
}

// ---------------- scatter both passes: vector atomics ----------------
__global__ void __launch_bounds__(256) k_scatter2(const int* __restrict__ e0,
        const int* __restrict__ e1, const float* __restrict__ Ma,
        const float* __restrict__ Mb, float* __restrict__ SUMa,
        float* __restrict__ SUMb, float* __restrict__ CNTa, float* __restrict__ CNTb) {
    int gw = (blockIdx.x * 256 + threadIdx.x) >> 5;
    int lane = threadIdx.x & 31;
    int pass = gw >> 19;
    int e = gw & 524287;
    int b = e >> 14;
    const int* eidx = pass ? e1 : e0;
    const float* m = pass ? Mb : Ma;
    float* sum = pass ? SUMb : SUMa;
    float* cnt = pass ? CNTb : CNTa;
    int2 ab = __ldg((const int2*)eidx + e);
    size_t basea = ((size_t)b * NNODE + ab.x) * 128;
    size_t baseb = ((size_t)b * NNODE + ab.y) * 128;
    float4 va = __ldg((const float4*)(m + basea) + lane);
    float4 vb = __ldg((const float4*)(m + baseb) + lane);
    red4(sum + basea + lane * 4, vb);
    red4(sum + baseb + lane * 4, va);
    if (lane == 0)      atomicAdd(cnt + b * NNODE + ab.x, 1.0f);
    else if (lane == 1) atomicAdd(cnt + b * NNODE + ab.y, 1.0f);
}

// ---------------- build comb = [h | sum*rcp] for both passes ----------------
__global__ void __launch_bounds__(256) k_comb(const float* __restrict__ h,
        const float* __restrict__ SUMa, const float* __restrict__ SUMb,
        const float* __restrict__ CNTa, const float* __restrict__ CNTb,
        float* __restrict__ COMBa, float* __restrict__ COMBb) {
    int i = blockIdx.x * 256 + threadIdx.x;   // 2 * 32768 * 32
    int pass = i >= 1048576;
    int j = pass ? i - 1048576 : i;
    int row = j >> 5, q = j & 31;
    const float* sum = pass ? SUMb : SUMa;
    const float* cnt = pass ? CNTb : CNTa;
    float* comb = pass ? COMBb : COMBa;
    float rcp = __fdividef(1.0f, __ldg(cnt + row) + EPS_F);
    float4 hv = __ldg((const float4*)(h + (size_t)row * 128) + q);
    float4 sv = __ldg((const float4*)(sum + (size_t)row * 128) + q);
    sv.x *= rcp; sv.y *= rcp; sv.z *= rcp; sv.w *= rcp;
    *(float4*)(comb + (size_t)row * 256 + q * 4) = hv;
    *(float4*)(comb + (size_t)row * 256 + 128 + q * 4) = sv;
}

// ---------------- gate combine: hc = g*u + (1-g)*h ----------------
__global__ void __launch_bounds__(256) k_gcomb(const float* __restrict__ GTa,
        const float* __restrict__ UTa, const float* __restrict__ GTb,
        const float* __restrict__ UTb, const float* __restrict__ h,
        float* __restrict__ hc) {
    int i = blockIdx.x * 256 + threadIdx.x;
    int pass = i >= 1048576;
    int j = pass ? i - 1048576 : i;
    int row = j >> 5, q = j & 31;
    const float* GT = pass ? GTb : GTa;
    const float* UT = pass ? UTb : UTa;
    float4 g = __ldg((const float4*)(GT + (size_t)row * 128) + q);
    float4 u = __ldg((const float4*)(UT + (size_t)row * 128) + q);
    float4 hv = __ldg((const float4*)(h + (size_t)row * 128) + q);
    float4 o;
    o.x = g.x * u.x + (1.0f - g.x) * hv.x;
    o.y = g.y * u.y + (1.0f - g.y) * hv.y;
    o.z = g.z * u.z + (1.0f - g.z) * hv.z;
    o.w = g.w * u.w + (1.0f - g.w) * hv.w;
    *(float4*)(hc + (size_t)row * 256 + pass * 128 + q * 4) = o;
}

// ---------------- fold W_in into Wq1/Wk1/Wv1 ----------------
__global__ void k_fuseW(const float* __restrict__ Wq1, const float* __restrict__ bq1,
                        const float* __restrict__ Wk1, const float* __restrict__ bk1,
                        const float* __restrict__ Wv1, const float* __restrict__ bv1,
                        const float* __restrict__ W_in, const float* __restrict__ b_in,
                        float* __restrict__ S) {
    int mat = blockIdx.y, r = blockIdx.x, c = threadIdx.x;
    const float* Wsrc = mat == 0 ? Wq1 : (mat == 1 ? Wk1 : Wv1);
    const float* bsrc = mat == 0 ? bq1 : (mat == 1 ? bk1 : bv1);
    float* Wd = S + (mat == 0 ? OFF_WQF : (mat == 1 ? OFF_WKF : OFF_WVF));
    float* bd = S + (mat == 0 ? OFF_BQF : (mat == 1 ? OFF_BKF : OFF_BVF));
    __shared__ float row[128];
    row[c] = (r < 256) ? Wsrc[r * 128 + c] : bsrc[c];
    __syncthreads();
    float a = 0.f;
    #pragma unroll 8
    for (int k = 0; k < 128; k++) a += row[k] * W_in[k * 384 + mat * 128 + c];
    if (r < 256) Wd[r * 128 + c] = a;
    else bd[c] = a + b_in[mat * 128 + c];
}

// ---------------- attention ----------------
__global__ void __launch_bounds__(512) k_attn(const float* __restrict__ q2,
        const float* __restrict__ k2, const float* __restrict__ v2,
        float* __restrict__ oh) {
    int h = blockIdx.x, b = blockIdx.y;
    __shared__ float Ks[256][17];
    __shared__ float Vs[256][17];
    int tid = threadIdx.x;
    for (int i = tid; i < 256 * 16; i += 512) {
        int k = i >> 4, d = i & 15;
        Ks[k][d] = k2[((size_t)b * 256 + k) * 128 + h * 16 + d];
        Vs[k][d] = v2[((size_t)b * 256 + k) * 128 + h * 16 + d];
    }
    __syncthreads();
    int warp = tid >> 5, lane = tid & 31;
    for (int q = warp; q < 1024; q += 16) {
        const float* qp = q2 + ((size_t)b * 1024 + q) * 128 + h * 16;
        float qv[16];
        #pragma unroll
        for (int d = 0; d < 16; d++) qv[d] = __ldg(qp + d);
        float s[8];
        #pragma unroll
        for (int j = 0; j < 8; j++) {
            int key = lane + 32 * j;
            float a = 0.f;
            #pragma unroll
            for (int d = 0; d < 16; d++) a += qv[d] * Ks[key][d];
            s[j] = a * 0.25f;
        }
        float mx = s[0];
        #pragma unroll
        for (int j = 1; j < 8; j++) mx = fmaxf(mx, s[j]);
        #pragma unroll
        for (int o = 16; o > 0; o >>= 1) mx = fmaxf(mx, __shfl_xor_sync(0xffffffffu, mx, o));
        float sm = 0.f;
        #pragma unroll
        for (int j = 0; j < 8; j++) { s[j] = __expf(s[j] - mx); sm += s[j]; }
        #pragma unroll
        for (int o = 16; o > 0; o >>= 1) sm += __shfl_xor_sync(0xffffffffu, sm, o);
        float inv = __fdividef(1.0f, sm);
        float acc[16];
        #pragma unroll
        for (int d = 0; d < 16; d++) acc[d] = 0.f;
        #pragma unroll
        for (int j = 0; j < 8; j++) {
            int key = lane + 32 * j;
            float p = s[j];
            #pragma unroll
            for (int d = 0; d < 16; d++) acc[d] += p * Vs[key][d];
        }
        #pragma unroll
        for (int d = 0; d < 16; d++) {
            #pragma unroll
            for (int o = 16; o > 0; o >>= 1) acc[d] += __shfl_xor_sync(0xffffffffu, acc[d], o);
            acc[d] *= inv;
        }
        if (lane == 0) {
            float* op = oh + ((size_t)b * 1024 + q) * 128 + h * 16;
            #pragma unroll
            for (int d = 0; d < 16; d++) op[d] = acc[d];
        }
    }
}

// ---------------- state_value + mask + stage ----------------
__global__ void k_final(const float* __restrict__ hnum, const float* __restrict__ hatt,
                        const float* __restrict__ stage, float* __restrict__ out) {
    int b = blockIdx.x, t = threadIdx.x;
    float* sv = out + 4194304 + (size_t)b * 258;
    __shared__ float part[256];
    {
        int c = t & 127, half = t >> 7;
        const float* p = hatt + (size_t)b * 131072 + (size_t)half * 512 * 128 + c;
        float s = 0.f;
        for (int n = 0; n < 512; n++) s += p[(size_t)n * 128];
        part[t] = s;
    }
    __syncthreads();
    if (t < 128) {
        sv[t] = hnum[b * 128 + t];
        sv[128 + t] = (part[t] + part[t + 128]) * (1.0f / 1024.0f);
    }
    if (t < 2) {
        sv[256 + t] = stage[b * 2 + t];
        out[4235328 + b * 2 + t] = stage[b * 2 + t];
    }
    for (int i = t; i < 1024; i += 256) out[4202560 + b * 1024 + i] = 1.0f;
}

extern "C" void kernel_launch(void* const* d_in, const int* in_sizes, int n_in,
                              void* d_out, int out_size) {
    const float* numerical = (const float*)d_in[0];
    const float* node_feature = (const float*)d_in[1];
    const float* stage = (const float*)d_in[2];
    const float* W_num0 = (const float*)d_in[3];
    const float* b_num0 = (const float*)d_in[4];
    const float* W_num1 = (const float*)d_in[5];
    const float* b_num1 = (const float*)d_in[6];
    const float* W_node = (const float*)d_in[7];
    const float* b_node = (const float*)d_in[8];
    const float* pos_enc = (const float*)d_in[9];
    const float* ew1 = (const float*)d_in[10];
    const float* eb1 = (const float*)d_in[11];
    const float* ew2 = (const float*)d_in[12];
    const float* eb2 = (const float*)d_in[13];
    const float* Wg = (const float*)d_in[14];
    const float* bg = (const float*)d_in[15];
    const float* Wu = (const float*)d_in[16];
    const float* bu = (const float*)d_in[17];
    const float* Wq1 = (const float*)d_in[18];
    const float* bq1 = (const float*)d_in[19];
    const float* Wk1 = (const float*)d_in[20];
    const float* bk1 = (const float*)d_in[21];
    const float* Wv1 = (const float*)d_in[22];
    const float* bv1 = (const float*)d_in[23];
    const float* W_in = (const float*)d_in[24];
    const float* b_in = (const float*)d_in[25];
    const float* W_out = (const float*)d_in[26];
    const float* b_out = (const float*)d_in[27];
    const int* e_dis = (const int*)d_in[28];
    const int* e_od = (const int*)d_in[29];
    const int* build_idx = (const int*)d_in[31];
    float* out = (float*)d_out;

    float* S = nullptr;
    cudaGetSymbolAddress((void**)&S, g_scratch);
    float* H    = S + OFF_H;
    float* T0a  = S + OFF_T0A;
    float* T0b  = S + OFF_T0B;
    float* Ma   = S + OFF_MA;
    float* Mb   = S + OFF_MB;
    float* SUMa = S + OFF_SUMA;
    float* SUMb = S + OFF_SUMB;
    float* CNTa = S + OFF_CNTA;
    float* CNTb = S + OFF_CNTB;
    float* COMBa = S + OFF_COMBA;
    float* COMBb = S + OFF_COMBB;
    float* GTa  = S + OFF_GTA;
    float* UTa  = S + OFF_UTA;
    float* GTb  = S + OFF_GTB;
    float* UTb  = S + OFF_UTB;
    float* HC   = S + OFF_HC;
    float* Q2   = S + OFF_Q2;
    float* K2   = S + OFF_K2;
    float* V2   = S + OFF_V2;
    float* OH   = S + OFF_OH;
    float* HNUM = S + OFF_HNUM;

    const int BIG = 1 << 30;

    k_hnum<<<32, 256>>>(numerical, W_num0, b_num0, W_num1, b_num1, HNUM);
    k_embed<<<4096, 128>>>(node_feature, W_node, b_node, pos_enc, H);
    k_fuseW<<<dim3(257, 3), 128>>>(Wq1, bq1, Wk1, bk1, Wv1, bv1, W_in, b_in, S);

    // edge-MLP layer 1 (only surviving L_GCN iteration), both passes batched
    {
        Jobs j = {};
        j.X[0] = H;   j.W[0] = ew1 + 2 * 16384; j.B[0] = eb1 + 2 * 128; j.Y[0] = T0a;
        j.X[1] = H;   j.W[1] = ew2 + 2 * 16384; j.B[1] = eb2 + 2 * 128; j.Y[1] = T0b;
        gemm128<<<dim3(256, 2), 256>>>(j, 128, BIG, 0, nullptr, 128, 128, 1);
    }
    {
        Jobs j = {};
        j.X[0] = T0a; j.W[0] = ew1 + 3 * 16384; j.B[0] = eb1 + 3 * 128; j.Y[0] = Ma;
        j.X[1] = T0b; j.W[1] = ew2 + 3 * 16384; j.B[1] = eb2 + 3 * 128; j.Y[1] = Mb;
        gemm128<<<dim3(256, 2), 256>>>(j, 128, BIG, 0, nullptr, 128, 128, 1);
    }

    cudaMemsetAsync(SUMa, 0, (2 * 4194304 + 2 * 32768) * sizeof(float));
    k_scatter2<<<131072, 256>>>(e_dis, e_od, Ma, Mb, SUMa, SUMb, CNTa, CNTb);
    k_comb<<<8192, 256>>>(H, SUMa, SUMb, CNTa, CNTb, COMBa, COMBb);

    // gate/update GEMMs for both passes (4 jobs)
    {
        Jobs j = {};
        j.X[0] = COMBa; j.W[0] = Wg; j.B[0] = bg; j.Y[0] = GTa;
        j.X[1] = COMBa; j.W[1] = Wu; j.B[1] = bu; j.Y[1] = UTa;
        j.X[2] = COMBb; j.W[2] = Wg; j.B[2] = bg; j.Y[2] = GTb;
        j.X[3] = COMBb; j.W[3] = Wu; j.B[3] = bu; j.Y[3] = UTb;
        gemm128<<<dim3(256, 4), 256>>>(j, 256, BIG, 0, nullptr, 128, 256, 1);
    }
    k_gcomb<<<8192, 256>>>(GTa, UTa, GTb, UTb, H, HC);

    {
        Jobs j = {};
        j.X[0] = HC; j.W[0] = S + OFF_WQF; j.B[0] = S + OFF_BQF; j.Y[0] = Q2;
        gemm128<<<dim3(256, 1), 256>>>(j, 256, BIG, 0, nullptr, 128, 256, 0);
    }
    {
        Jobs j = {};
        j.X[0] = HC; j.W[0] = S + OFF_WKF; j.B[0] = S + OFF_BKF; j.Y[0] = K2;
        j.X[1] = HC; j.W[1] = S + OFF_WVF; j.B[1] = S + OFF_BVF; j.Y[1] = V2;
        gemm128<<<dim3(64, 2), 256>>>(j, 256, 256, 262144, build_idx, 128, 256, 0);
    }
    k_attn<<<dim3(8, 32), 512>>>(Q2, K2, V2, OH);
    {
        Jobs j = {};
        j.X[0] = OH; j.W[0] = W_out; j.B[0] = b_out; j.Y[0] = out;
        gemm128<<<dim3(256, 1), 256>>>(j, 128, BIG, 0, nullptr, 128, 128, 0);
    }
    k_final<<<32, 256>>>(HNUM, out, stage, out);
}

// round 5
// speedup vs baseline: 1.9894x; 1.9894x over previous
#include <cuda_runtime.h>
#include <math.h>

#define NNODE 1024
#define EPS_F 1e-6f

// ---- scratch layout (floats) ----
#define OFF_H     ((size_t)0)
#define OFF_T0A   (OFF_H    + 4194304)
#define OFF_T0B   (OFF_T0A  + 4194304)
#define OFF_MA    (OFF_T0B  + 4194304)
#define OFF_MB    (OFF_MA   + 4194304)
#define OFF_SUMA  (OFF_MB   + 4194304)
#define OFF_SUMB  (OFF_SUMA + 4194304)
#define OFF_CNTA  (OFF_SUMB + 4194304)
#define OFF_CNTB  (OFF_CNTA + 32768)
#define OFF_COMBA (OFF_CNTB + 32768)
#define OFF_COMBB (OFF_COMBA + 8388608)
#define OFF_GTA   (OFF_COMBB + 8388608)
#define OFF_UTA   (OFF_GTA  + 4194304)
#define OFF_GTB   (OFF_UTA  + 4194304)
#define OFF_UTB   (OFF_GTB  + 4194304)
#define OFF_HC    (OFF_UTB  + 4194304)
#define OFF_Q2    (OFF_HC   + 8388608)
#define OFF_K2    (OFF_Q2   + 4194304)
#define OFF_V2    (OFF_K2   + 1048576)
#define OFF_OH    (OFF_V2   + 1048576)
#define OFF_HNUM  (OFF_OH   + 4194304)
#define OFF_WQF   (OFF_HNUM + 4096)
#define OFF_BQF   (OFF_WQF  + 32768)
#define OFF_WKF   (OFF_BQF  + 128)
#define OFF_BKF   (OFF_WKF  + 32768)
#define OFF_WVF   (OFF_BKF  + 128)
#define OFF_BVF   (OFF_WVF  + 32768)
#define SCRATCH_FLOATS (OFF_BVF + 128)

__device__ float g_scratch[SCRATCH_FLOATS];

__device__ __forceinline__ float ftanh(float x) {
    float t = __expf(2.0f * x);
    return 1.0f - __fdividef(2.0f, t + 1.0f);
}

__device__ __forceinline__ void red4(float* p, float4 v) {
    asm volatile("red.global.v4.f32.add [%0], {%1,%2,%3,%4};"
        :: "l"(p), "f"(v.x), "f"(v.y), "f"(v.z), "f"(v.w) : "memory");
}

__device__ __forceinline__ float to_tf32(float x) {
    unsigned u;
    asm("cvt.rna.tf32.f32 %0, %1;" : "=r"(u) : "f"(x));
    return __uint_as_float(u);
}

__device__ __forceinline__ void mma8(float4& c, const unsigned* a, unsigned b0, unsigned b1) {
    asm volatile("mma.sync.aligned.m16n8k8.row.col.f32.tf32.tf32.f32 "
        "{%0,%1,%2,%3}, {%4,%5,%6,%7}, {%8,%9}, {%0,%1,%2,%3};"
        : "+f"(c.x), "+f"(c.y), "+f"(c.z), "+f"(c.w)
        : "r"(a[0]), "r"(a[1]), "r"(a[2]), "r"(a[3]), "r"(b0), "r"(b1));
}

// ---------------- h_num ----------------
__global__ void k_hnum(const float* __restrict__ num, const float* __restrict__ W0,
                       const float* __restrict__ b0, const float* __restrict__ W1,
                       const float* __restrict__ b1, float* __restrict__ out) {
    __shared__ float xs[64];
    __shared__ float hid[256];
    int b = blockIdx.x, t = threadIdx.x;
    if (t < 64) xs[t] = num[b * 64 + t];
    __syncthreads();
    float a = b0[t];
    #pragma unroll 8
    for (int k = 0; k < 64; k++) a += xs[k] * W0[k * 256 + t];
    hid[t] = ftanh(a);
    __syncthreads();
    if (t < 128) {
        float a2 = b1[t];
        #pragma unroll 8
        for (int k = 0; k < 256; k++) a2 += hid[k] * W1[k * 128 + t];
        out[b * 128 + t] = ftanh(a2);
    }
}

// ---------------- node embed ----------------
__global__ void __launch_bounds__(128) k_embed(const float* __restrict__ nf,
        const float* __restrict__ Wn, const float* __restrict__ bn,
        const float* __restrict__ pos, float* __restrict__ h) {
    __shared__ float ws[4096];
    __shared__ float xs[256];
    int t = threadIdx.x;
    int rbase = blockIdx.x * 8;
    for (int i = t; i < 4096; i += 128) ws[i] = Wn[i];
    for (int i = t; i < 256; i += 128) xs[i] = nf[(size_t)rbase * 32 + i];
    __syncthreads();
    float bv = bn[t];
    #pragma unroll
    for (int r = 0; r < 8; r++) {
        float a = bv;
        #pragma unroll 8
        for (int k = 0; k < 32; k++) a += xs[r * 32 + k] * ws[k * 128 + t];
        int row = rbase + r;
        h[(size_t)row * 128 + t] = ftanh(a) + pos[(size_t)(row & 1023) * 128 + t];
    }
}

// ---------------- batched tf32 tensor-core GEMM: 128x128 tile ----------------
struct Jobs {
    const float* X[4];
    const float* W[4];
    const float* B[4];
    float* Y[4];
};

__global__ void __launch_bounds__(256, 2) gemm_tc(Jobs jobs, int ldx, int rpb,
        size_t bstride, const int* __restrict__ rowmap, int ldy, int K, int act) {
    const float* __restrict__ X = jobs.X[blockIdx.y];
    const float* __restrict__ W = jobs.W[blockIdx.y];
    const float* __restrict__ bias = jobs.B[blockIdx.y];
    float* __restrict__ Y = jobs.Y[blockIdx.y];
    __shared__ float Xs[32][133];
    __shared__ float Ws[32][132];
    __shared__ unsigned rowoff[128];
    int tid = threadIdx.x;
    int rbase = blockIdx.x * 128;
    if (tid < 128) {
        int r = rbase + tid;
        int bb = r / rpb;
        int n = r - bb * rpb;
        if (rowmap) n = rowmap[n];
        rowoff[tid] = (unsigned)((size_t)bb * bstride + (size_t)n * ldx);
    }
    __syncthreads();
    int wid = tid >> 5, lane = tid & 31;
    int wm = (wid & 3) * 32;        // warp m-offset
    int wn = (wid >> 2) * 64;       // warp n-offset
    int gid = lane >> 2, tig = lane & 3;
    float4 c[2][8];
    #pragma unroll
    for (int i = 0; i < 2; i++)
        #pragma unroll
        for (int j = 0; j < 8; j++) c[i][j] = make_float4(0.f, 0.f, 0.f, 0.f);

    int xr = tid >> 1, xh = (tid & 1) * 16;
    for (int kb = 0; kb < K; kb += 32) {
        // stage X (transposed, tf32-rounded): Xs[k][m]
        #pragma unroll
        for (int p = 0; p < 4; p++) {
            float4 v = *(const float4*)(X + rowoff[xr] + kb + xh + p * 4);
            Xs[xh + p * 4 + 0][xr] = to_tf32(v.x);
            Xs[xh + p * 4 + 1][xr] = to_tf32(v.y);
            Xs[xh + p * 4 + 2][xr] = to_tf32(v.z);
            Xs[xh + p * 4 + 3][xr] = to_tf32(v.w);
        }
        // stage W: Ws[k][n]
        #pragma unroll
        for (int p = 0; p < 4; p++) {
            int idx = p * 256 + tid;
            int k = idx >> 5, n4 = (idx & 31) * 4;
            float4 v = *(const float4*)(W + (size_t)(kb + k) * 128 + n4);
            v.x = to_tf32(v.x); v.y = to_tf32(v.y);
            v.z = to_tf32(v.z); v.w = to_tf32(v.w);
            *(float4*)&Ws[k][n4] = v;
        }
        __syncthreads();
        #pragma unroll
        for (int ks = 0; ks < 4; ks++) {
            int kk = ks * 8;
            unsigned a[2][4];
            #pragma unroll
            for (int mt = 0; mt < 2; mt++) {
                int m = wm + mt * 16 + gid;
                a[mt][0] = __float_as_uint(Xs[kk + tig][m]);
                a[mt][1] = __float_as_uint(Xs[kk + tig][m + 8]);
                a[mt][2] = __float_as_uint(Xs[kk + tig + 4][m]);
                a[mt][3] = __float_as_uint(Xs[kk + tig + 4][m + 8]);
            }
            #pragma unroll
            for (int nt = 0; nt < 8; nt++) {
                int n = wn + nt * 8 + gid;
                unsigned b0 = __float_as_uint(Ws[kk + tig][n]);
                unsigned b1 = __float_as_uint(Ws[kk + tig + 4][n]);
                mma8(c[0][nt], a[0], b0, b1);
                mma8(c[1][nt], a[1], b0, b1);
            }
        }
        __syncthreads();
    }
    // epilogue: bias + act, float2 stores
    #pragma unroll
    for (int nt = 0; nt < 8; nt++) {
        int col = wn + nt * 8 + tig * 2;
        float bz0 = bias[col], bz1 = bias[col + 1];
        #pragma unroll
        for (int mt = 0; mt < 2; mt++) {
            int row0 = rbase + wm + mt * 16 + gid;
            float4 cc = c[mt][nt];
            float o00 = cc.x + bz0, o01 = cc.y + bz1;
            float o10 = cc.z + bz0, o11 = cc.w + bz1;
            if (act) { o00 = ftanh(o00); o01 = ftanh(o01); o10 = ftanh(o10); o11 = ftanh(o11); }
            *(float2*)(Y + (size_t)row0 * ldy + col) = make_float2(o00, o01);
            *(float2*)(Y + (size_t)(row0 + 8) * ldy + col) = make_float2(o10, o11);
        }
    }
}

// ---------------- scatter both passes: vector atomics ----------------
__global__ void __launch_bounds__(256) k_scatter2(const int* __restrict__ e0,
        const int* __restrict__ e1, const float* __restrict__ Ma,
        const float* __restrict__ Mb, float* __restrict__ SUMa,
        float* __restrict__ SUMb, float* __restrict__ CNTa, float* __restrict__ CNTb) {
    int gw = (blockIdx.x * 256 + threadIdx.x) >> 5;
    int lane = threadIdx.x & 31;
    int pass = gw >> 19;
    int e = gw & 524287;
    int b = e >> 14;
    const int* eidx = pass ? e1 : e0;
    const float* m = pass ? Mb : Ma;
    float* sum = pass ? SUMb : SUMa;
    float* cnt = pass ? CNTb : CNTa;
    int2 ab = __ldg((const int2*)eidx + e);
    size_t basea = ((size_t)b * NNODE + ab.x) * 128;
    size_t baseb = ((size_t)b * NNODE + ab.y) * 128;
    float4 va = __ldg((const float4*)(m + basea) + lane);
    float4 vb = __ldg((const float4*)(m + baseb) + lane);
    red4(sum + basea + lane * 4, vb);
    red4(sum + baseb + lane * 4, va);
    if (lane == 0)      atomicAdd(cnt + b * NNODE + ab.x, 1.0f);
    else if (lane == 1) atomicAdd(cnt + b * NNODE + ab.y, 1.0f);
}

// ---------------- build comb = [h | sum*rcp] ----------------
__global__ void __launch_bounds__(256) k_comb(const float* __restrict__ h,
        const float* __restrict__ SUMa, const float* __restrict__ SUMb,
        const float* __restrict__ CNTa, const float* __restrict__ CNTb,
        float* __restrict__ COMBa, float* __restrict__ COMBb) {
    int i = blockIdx.x * 256 + threadIdx.x;
    int pass = i >= 1048576;
    int j = pass ? i - 1048576 : i;
    int row = j >> 5, q = j & 31;
    const float* sum = pass ? SUMb : SUMa;
    const float* cnt = pass ? CNTb : CNTa;
    float* comb = pass ? COMBb : COMBa;
    float rcp = __fdividef(1.0f, __ldg(cnt + row) + EPS_F);
    float4 hv = __ldg((const float4*)(h + (size_t)row * 128) + q);
    float4 sv = __ldg((const float4*)(sum + (size_t)row * 128) + q);
    sv.x *= rcp; sv.y *= rcp; sv.z *= rcp; sv.w *= rcp;
    *(float4*)(comb + (size_t)row * 256 + q * 4) = hv;
    *(float4*)(comb + (size_t)row * 256 + 128 + q * 4) = sv;
}

// ---------------- gate combine ----------------
__global__ void __launch_bounds__(256) k_gcomb(const float* __restrict__ GTa,
        const float* __restrict__ UTa, const float* __restrict__ GTb,
        const float* __restrict__ UTb, const float* __restrict__ h,
        float* __restrict__ hc) {
    int i = blockIdx.x * 256 + threadIdx.x;
    int pass = i >= 1048576;
    int j = pass ? i - 1048576 : i;
    int row = j >> 5, q = j & 31;
    const float* GT = pass ? GTb : GTa;
    const float* UT = pass ? UTb : UTa;
    float4 g = __ldg((const float4*)(GT + (size_t)row * 128) + q);
    float4 u = __ldg((const float4*)(UT + (size_t)row * 128) + q);
    float4 hv = __ldg((const float4*)(h + (size_t)row * 128) + q);
    float4 o;
    o.x = g.x * u.x + (1.0f - g.x) * hv.x;
    o.y = g.y * u.y + (1.0f - g.y) * hv.y;
    o.z = g.z * u.z + (1.0f - g.z) * hv.z;
    o.w = g.w * u.w + (1.0f - g.w) * hv.w;
    *(float4*)(hc + (size_t)row * 256 + pass * 128 + q * 4) = o;
}

// ---------------- fold W_in into Wq1/Wk1/Wv1 ----------------
__global__ void k_fuseW(const float* __restrict__ Wq1, const float* __restrict__ bq1,
                        const float* __restrict__ Wk1, const float* __restrict__ bk1,
                        const float* __restrict__ Wv1, const float* __restrict__ bv1,
                        const float* __restrict__ W_in, const float* __restrict__ b_in,
                        float* __restrict__ S) {
    int mat = blockIdx.y, r = blockIdx.x, c = threadIdx.x;
    const float* Wsrc = mat == 0 ? Wq1 : (mat == 1 ? Wk1 : Wv1);
    const float* bsrc = mat == 0 ? bq1 : (mat == 1 ? bk1 : bv1);
    float* Wd = S + (mat == 0 ? OFF_WQF : (mat == 1 ? OFF_WKF : OFF_WVF));
    float* bd = S + (mat == 0 ? OFF_BQF : (mat == 1 ? OFF_BKF : OFF_BVF));
    __shared__ float row[128];
    row[c] = (r < 256) ? Wsrc[r * 128 + c] : bsrc[c];
    __syncthreads();
    float a = 0.f;
    #pragma unroll 8
    for (int k = 0; k < 128; k++) a += row[k] * W_in[k * 384 + mat * 128 + c];
    if (r < 256) Wd[r * 128 + c] = a;
    else bd[c] = a + b_in[mat * 128 + c];
}

// ---------------- attention ----------------
__global__ void __launch_bounds__(512) k_attn(const float* __restrict__ q2,
        const float* __restrict__ k2, const float* __restrict__ v2,
        float* __restrict__ oh) {
    int h = blockIdx.x, b = blockIdx.y;
    __shared__ float Ks[256][17];
    __shared__ float Vs[256][17];
    int tid = threadIdx.x;
    for (int i = tid; i < 256 * 16; i += 512) {
        int k = i >> 4, d = i & 15;
        Ks[k][d] = k2[((size_t)b * 256 + k) * 128 + h * 16 + d];
        Vs[k][d] = v2[((size_t)b * 256 + k) * 128 + h * 16 + d];
    }
    __syncthreads();
    int warp = tid >> 5, lane = tid & 31;
    for (int q = warp; q < 1024; q += 16) {
        const float* qp = q2 + ((size_t)b * 1024 + q) * 128 + h * 16;
        float qv[16];
        #pragma unroll
        for (int d = 0; d < 16; d++) qv[d] = __ldg(qp + d);
        float s[8];
        #pragma unroll
        for (int j = 0; j < 8; j++) {
            int key = lane + 32 * j;
            float a = 0.f;
            #pragma unroll
            for (int d = 0; d < 16; d++) a += qv[d] * Ks[key][d];
            s[j] = a * 0.25f;
        }
        float mx = s[0];
        #pragma unroll
        for (int j = 1; j < 8; j++) mx = fmaxf(mx, s[j]);
        #pragma unroll
        for (int o = 16; o > 0; o >>= 1) mx = fmaxf(mx, __shfl_xor_sync(0xffffffffu, mx, o));
        float sm = 0.f;
        #pragma unroll
        for (int j = 0; j < 8; j++) { s[j] = __expf(s[j] - mx); sm += s[j]; }
        #pragma unroll
        for (int o = 16; o > 0; o >>= 1) sm += __shfl_xor_sync(0xffffffffu, sm, o);
        float inv = __fdividef(1.0f, sm);
        float acc[16];
        #pragma unroll
        for (int d = 0; d < 16; d++) acc[d] = 0.f;
        #pragma unroll
        for (int j = 0; j < 8; j++) {
            int key = lane + 32 * j;
            float p = s[j];
            #pragma unroll
            for (int d = 0; d < 16; d++) acc[d] += p * Vs[key][d];
        }
        #pragma unroll
        for (int d = 0; d < 16; d++) {
            #pragma unroll
            for (int o = 16; o > 0; o >>= 1) acc[d] += __shfl_xor_sync(0xffffffffu, acc[d], o);
            acc[d] *= inv;
        }
        if (lane == 0) {
            float* op = oh + ((size_t)b * 1024 + q) * 128 + h * 16;
            #pragma unroll
            for (int d = 0; d < 16; d++) op[d] = acc[d];
        }
    }
}

// ---------------- state_value + mask + stage ----------------
__global__ void k_final(const float* __restrict__ hnum, const float* __restrict__ hatt,
                        const float* __restrict__ stage, float* __restrict__ out) {
    int b = blockIdx.x, t = threadIdx.x;
    float* sv = out + 4194304 + (size_t)b * 258;
    __shared__ float part[256];
    {
        int c = t & 127, half = t >> 7;
        const float* p = hatt + (size_t)b * 131072 + (size_t)half * 512 * 128 + c;
        float s = 0.f;
        for (int n = 0; n < 512; n++) s += p[(size_t)n * 128];
        part[t] = s;
    }
    __syncthreads();
    if (t < 128) {
        sv[t] = hnum[b * 128 + t];
        sv[128 + t] = (part[t] + part[t + 128]) * (1.0f / 1024.0f);
    }
    if (t < 2) {
        sv[256 + t] = stage[b * 2 + t];
        out[4235328 + b * 2 + t] = stage[b * 2 + t];
    }
    for (int i = t; i < 1024; i += 256) out[4202560 + b * 1024 + i] = 1.0f;
}

extern "C" void kernel_launch(void* const* d_in, const int* in_sizes, int n_in,
                              void* d_out, int out_size) {
    const float* numerical = (const float*)d_in[0];
    const float* node_feature = (const float*)d_in[1];
    const float* stage = (const float*)d_in[2];
    const float* W_num0 = (const float*)d_in[3];
    const float* b_num0 = (const float*)d_in[4];
    const float* W_num1 = (const float*)d_in[5];
    const float* b_num1 = (const float*)d_in[6];
    const float* W_node = (const float*)d_in[7];
    const float* b_node = (const float*)d_in[8];
    const float* pos_enc = (const float*)d_in[9];
    const float* ew1 = (const float*)d_in[10];
    const float* eb1 = (const float*)d_in[11];
    const float* ew2 = (const float*)d_in[12];
    const float* eb2 = (const float*)d_in[13];
    const float* Wg = (const float*)d_in[14];
    const float* bg = (const float*)d_in[15];
    const float* Wu = (const float*)d_in[16];
    const float* bu = (const float*)d_in[17];
    const float* Wq1 = (const float*)d_in[18];
    const float* bq1 = (const float*)d_in[19];
    const float* Wk1 = (const float*)d_in[20];
    const float* bk1 = (const float*)d_in[21];
    const float* Wv1 = (const float*)d_in[22];
    const float* bv1 = (const float*)d_in[23];
    const float* W_in = (const float*)d_in[24];
    const float* b_in = (const float*)d_in[25];
    const float* W_out = (const float*)d_in[26];
    const float* b_out = (const float*)d_in[27];
    const int* e_dis = (const int*)d_in[28];
    const int* e_od = (const int*)d_in[29];
    const int* build_idx = (const int*)d_in[31];
    float* out = (float*)d_out;

    float* S = nullptr;
    cudaGetSymbolAddress((void**)&S, g_scratch);
    float* H    = S + OFF_H;
    float* T0a  = S + OFF_T0A;
    float* T0b  = S + OFF_T0B;
    float* Ma   = S + OFF_MA;
    float* Mb   = S + OFF_MB;
    float* SUMa = S + OFF_SUMA;
    float* SUMb = S + OFF_SUMB;
    float* CNTa = S + OFF_CNTA;
    float* CNTb = S + OFF_CNTB;
    float* COMBa = S + OFF_COMBA;
    float* COMBb = S + OFF_COMBB;
    float* GTa  = S + OFF_GTA;
    float* UTa  = S + OFF_UTA;
    float* GTb  = S + OFF_GTB;
    float* UTb  = S + OFF_UTB;
    float* HC   = S + OFF_HC;
    float* Q2   = S + OFF_Q2;
    float* K2   = S + OFF_K2;
    float* V2   = S + OFF_V2;
    float* OH   = S + OFF_OH;
    float* HNUM = S + OFF_HNUM;

    const int BIG = 1 << 30;

    k_hnum<<<32, 256>>>(numerical, W_num0, b_num0, W_num1, b_num1, HNUM);
    k_embed<<<4096, 128>>>(node_feature, W_node, b_node, pos_enc, H);
    k_fuseW<<<dim3(257, 3), 128>>>(Wq1, bq1, Wk1, bk1, Wv1, bv1, W_in, b_in, S);

    // edge-MLP layer 1 (only surviving L_GCN iteration), both passes batched
    {
        Jobs j = {};
        j.X[0] = H;   j.W[0] = ew1 + 2 * 16384; j.B[0] = eb1 + 2 * 128; j.Y[0] = T0a;
        j.X[1] = H;   j.W[1] = ew2 + 2 * 16384; j.B[1] = eb2 + 2 * 128; j.Y[1] = T0b;
        gemm_tc<<<dim3(256, 2), 256>>>(j, 128, BIG, 0, nullptr, 128, 128, 1);
    }
    {
        Jobs j = {};
        j.X[0] = T0a; j.W[0] = ew1 + 3 * 16384; j.B[0] = eb1 + 3 * 128; j.Y[0] = Ma;
        j.X[1] = T0b; j.W[1] = ew2 + 3 * 16384; j.B[1] = eb2 + 3 * 128; j.Y[1] = Mb;
        gemm_tc<<<dim3(256, 2), 256>>>(j, 128, BIG, 0, nullptr, 128, 128, 1);
    }

    cudaMemsetAsync(SUMa, 0, (2 * 4194304 + 2 * 32768) * sizeof(float));
    k_scatter2<<<131072, 256>>>(e_dis, e_od, Ma, Mb, SUMa, SUMb, CNTa, CNTb);
    k_comb<<<8192, 256>>>(H, SUMa, SUMb, CNTa, CNTb, COMBa, COMBb);

    // gate/update GEMMs for both passes (4 jobs)
    {
        Jobs j = {};
        j.X[0] = COMBa; j.W[0] = Wg; j.B[0] = bg; j.Y[0] = GTa;
        j.X[1] = COMBa; j.W[1] = Wu; j.B[1] = bu; j.Y[1] = UTa;
        j.X[2] = COMBb; j.W[2] = Wg; j.B[2] = bg; j.Y[2] = GTb;
        j.X[3] = COMBb; j.W[3] = Wu; j.B[3] = bu; j.Y[3] = UTb;
        gemm_tc<<<dim3(256, 4), 256>>>(j, 256, BIG, 0, nullptr, 128, 256, 1);
    }
    k_gcomb<<<8192, 256>>>(GTa, UTa, GTb, UTb, H, HC);

    {
        Jobs j = {};
        j.X[0] = HC; j.W[0] = S + OFF_WQF; j.B[0] = S + OFF_BQF; j.Y[0] = Q2;
        gemm_tc<<<dim3(256, 1), 256>>>(j, 256, BIG, 0, nullptr, 128, 256, 0);
    }
    {
        Jobs j = {};
        j.X[0] = HC; j.W[0] = S + OFF_WKF; j.B[0] = S + OFF_BKF; j.Y[0] = K2;
        j.X[1] = HC; j.W[1] = S + OFF_WVF; j.B[1] = S + OFF_BVF; j.Y[1] = V2;
        gemm_tc<<<dim3(64, 2), 256>>>(j, 256, 256, 262144, build_idx, 128, 256, 0);
    }
    k_attn<<<dim3(8, 32), 512>>>(Q2, K2, V2, OH);
    {
        Jobs j = {};
        j.X[0] = OH; j.W[0] = W_out; j.B[0] = b_out; j.Y[0] = out;
        gemm_tc<<<dim3(256, 1), 256>>>(j, 128, BIG, 0, nullptr, 128, 128, 0);
    }
    k_final<<<32, 256>>>(HNUM, out, stage, out);
}

// round 6
// speedup vs baseline: 2.2688x; 1.1404x over previous
#include <cuda_runtime.h>
#include <math.h>
#include <stdint.h>

#define NNODE 1024
#define EPS_F 1e-6f

// ---- scratch layout (floats) ----
#define OFF_H     ((size_t)0)
#define OFF_T0A   (OFF_H    + 4194304)
#define OFF_T0B   (OFF_T0A  + 4194304)
#define OFF_MA    (OFF_T0B  + 4194304)
#define OFF_MB    (OFF_MA   + 4194304)
#define OFF_SUMA  (OFF_MB   + 4194304)
#define OFF_SUMB  (OFF_SUMA + 4194304)
#define OFF_CNTA  (OFF_SUMB + 4194304)
#define OFF_CNTB  (OFF_CNTA + 32768)
#define OFF_GTA   (OFF_CNTB + 32768)
#define OFF_UTA   (OFF_GTA  + 4194304)
#define OFF_GTB   (OFF_UTA  + 4194304)
#define OFF_UTB   (OFF_GTB  + 4194304)
#define OFF_HC    (OFF_UTB  + 4194304)
#define OFF_Q2    (OFF_HC   + 8388608)
#define OFF_K2    (OFF_Q2   + 4194304)
#define OFF_V2    (OFF_K2   + 1048576)
#define OFF_OH    (OFF_V2   + 1048576)
#define OFF_HNUM  (OFF_OH   + 4194304)
#define OFF_WQF   (OFF_HNUM + 4096)
#define OFF_BQF   (OFF_WQF  + 32768)
#define OFF_WKF   (OFF_BQF  + 128)
#define OFF_BKF   (OFF_WKF  + 32768)
#define OFF_WVF   (OFF_BKF  + 128)
#define OFF_BVF   (OFF_WVF  + 32768)
#define SCRATCH_FLOATS (OFF_BVF + 128)

__device__ float g_scratch[SCRATCH_FLOATS];

__device__ __forceinline__ float ftanh(float x) {
    float t = __expf(2.0f * x);
    return 1.0f - __fdividef(2.0f, t + 1.0f);
}

__device__ __forceinline__ void red4(float* p, float4 v) {
    asm volatile("red.global.v4.f32.add [%0], {%1,%2,%3,%4};"
        :: "l"(p), "f"(v.x), "f"(v.y), "f"(v.z), "f"(v.w) : "memory");
}

__device__ __forceinline__ unsigned cvtu(float x) {
    unsigned u;
    asm("cvt.rna.tf32.f32 %0, %1;" : "=r"(u) : "f"(x));
    return u;
}

__device__ __forceinline__ void mma8(float4& c, const unsigned* a, unsigned b0, unsigned b1) {
    asm volatile("mma.sync.aligned.m16n8k8.row.col.f32.tf32.tf32.f32 "
        "{%0,%1,%2,%3}, {%4,%5,%6,%7}, {%8,%9}, {%0,%1,%2,%3};"
        : "+f"(c.x), "+f"(c.y), "+f"(c.z), "+f"(c.w)
        : "r"(a[0]), "r"(a[1]), "r"(a[2]), "r"(a[3]), "r"(b0), "r"(b1));
}

__device__ __forceinline__ void cpa16(void* s, const void* g) {
    unsigned sa = (unsigned)__cvta_generic_to_shared(s);
    asm volatile("cp.async.cg.shared.global [%0], [%1], 16;" :: "r"(sa), "l"(g));
}

// ---------------- h_num ----------------
__global__ void k_hnum(const float* __restrict__ num, const float* __restrict__ W0,
                       const float* __restrict__ b0, const float* __restrict__ W1,
                       const float* __restrict__ b1, float* __restrict__ out) {
    __shared__ float xs[64];
    __shared__ float hid[256];
    int b = blockIdx.x, t = threadIdx.x;
    if (t < 64) xs[t] = num[b * 64 + t];
    __syncthreads();
    float a = b0[t];
    #pragma unroll 8
    for (int k = 0; k < 64; k++) a += xs[k] * W0[k * 256 + t];
    hid[t] = ftanh(a);
    __syncthreads();
    if (t < 128) {
        float a2 = b1[t];
        #pragma unroll 8
        for (int k = 0; k < 256; k++) a2 += hid[k] * W1[k * 128 + t];
        out[b * 128 + t] = ftanh(a2);
    }
}

// ---------------- node embed ----------------
__global__ void __launch_bounds__(128) k_embed(const float* __restrict__ nf,
        const float* __restrict__ Wn, const float* __restrict__ bn,
        const float* __restrict__ pos, float* __restrict__ h) {
    __shared__ float ws[4096];
    __shared__ float xs[256];
    int t = threadIdx.x;
    int rbase = blockIdx.x * 8;
    for (int i = t; i < 4096; i += 128) ws[i] = Wn[i];
    for (int i = t; i < 256; i += 128) xs[i] = nf[(size_t)rbase * 32 + i];
    __syncthreads();
    float bv = bn[t];
    #pragma unroll
    for (int r = 0; r < 8; r++) {
        float a = bv;
        #pragma unroll 8
        for (int k = 0; k < 32; k++) a += xs[r * 32 + k] * ws[k * 128 + t];
        int row = rbase + r;
        h[(size_t)row * 128 + t] = ftanh(a) + pos[(size_t)(row & 1023) * 128 + t];
    }
}

// ---------------- batched tf32 GEMM: 128x128 tile, cp.async double buffer ----------------
// comb mode (SUM[j] != null): K=256, k<128 reads X (=h), k>=128 reads SUM, rcp(cnt) applied per-row
struct Jobs {
    const float* X[4];
    const float* W[4];
    const float* B[4];
    float* Y[4];
    const float* SUM[4];
    const float* CNT[4];
};

#define XPITCH 36
#define WPITCH 132
#define SM_XB (2 * 128 * XPITCH)               // floats
#define SM_WB (2 * 32 * WPITCH)
#define GEMM_SMEM_BYTES ((SM_XB + SM_WB + 128 + 128) * 4)

__global__ void __launch_bounds__(256, 2) gemm_tc(Jobs jobs, int ldx, int rpb,
        size_t bstride, const int* __restrict__ rowmap, int ldy, int K, int act) {
    extern __shared__ float sm[];
    float* Xs = sm;                        // [2][128][XPITCH]
    float* Ws = sm + SM_XB;                // [2][32][WPITCH]
    unsigned* rowoff = (unsigned*)(sm + SM_XB + SM_WB);
    float* rcps = (float*)(rowoff + 128);

    const float* __restrict__ X = jobs.X[blockIdx.y];
    const float* __restrict__ W = jobs.W[blockIdx.y];
    const float* __restrict__ bias = jobs.B[blockIdx.y];
    float* __restrict__ Y = jobs.Y[blockIdx.y];
    const float* __restrict__ SUM = jobs.SUM[blockIdx.y];
    const float* __restrict__ CNT = jobs.CNT[blockIdx.y];
    bool mode = (SUM != nullptr);

    int tid = threadIdx.x;
    int rbase = blockIdx.x * 128;
    if (tid < 128) {
        int r = rbase + tid;
        int bb = r / rpb;
        int n = r - bb * rpb;
        if (rowmap) n = rowmap[n];
        rowoff[tid] = (unsigned)((size_t)bb * bstride + (size_t)n * ldx);
        if (mode) rcps[tid] = __fdividef(1.0f, CNT[r] + EPS_F);
    }
    __syncthreads();

    int wid = tid >> 5, lane = tid & 31;
    int wm = (wid & 3) * 32;
    int wn = (wid >> 2) * 64;
    int gid = lane >> 2, tig = lane & 3;

    int xrow = tid >> 1;                   // 2 threads per row, 4 rows-worth per p step
    float4 c[2][8];
    #pragma unroll
    for (int i = 0; i < 2; i++)
        #pragma unroll
        for (int j = 0; j < 8; j++) c[i][j] = make_float4(0.f, 0.f, 0.f, 0.f);

    float rcp0[2], rcp1[2];
    #pragma unroll
    for (int mt = 0; mt < 2; mt++) {
        rcp0[mt] = mode ? rcps[wm + mt * 16 + gid] : 1.0f;
        rcp1[mt] = mode ? rcps[wm + mt * 16 + gid + 8] : 1.0f;
    }

    int nk = K >> 5;

    // staging lambda-ish macro
    #define STAGE(IB) do { \
        int kb_ = (IB) * 32; \
        int buf_ = (IB) & 1; \
        const float* xb_ = X; int ko_ = kb_; \
        if (mode && kb_ >= 128) { xb_ = SUM; ko_ = kb_ - 128; } \
        _Pragma("unroll") \
        for (int p_ = 0; p_ < 4; p_++) { \
            int id_ = p_ * 256 + tid; \
            int r_ = id_ >> 3, c_ = (id_ & 7) * 4; \
            cpa16(&Xs[buf_ * 128 * XPITCH + r_ * XPITCH + c_], xb_ + rowoff[r_] + ko_ + c_); \
        } \
        _Pragma("unroll") \
        for (int p_ = 0; p_ < 4; p_++) { \
            int id_ = p_ * 256 + tid; \
            int k_ = id_ >> 5, c_ = (id_ & 31) * 4; \
            cpa16(&Ws[buf_ * 32 * WPITCH + k_ * WPITCH + c_], W + (size_t)(kb_ + k_) * 128 + c_); \
        } \
    } while (0)

    STAGE(0);
    asm volatile("cp.async.commit_group;");

    for (int ib = 0; ib < nk; ib++) {
        if (ib + 1 < nk) {
            STAGE(ib + 1);
            asm volatile("cp.async.commit_group;");
            asm volatile("cp.async.wait_group 1;");
        } else {
            asm volatile("cp.async.wait_group 0;");
        }
        __syncthreads();
        int kb = ib * 32;
        float* Xb = Xs + (ib & 1) * 128 * XPITCH;
        float* Wb = Ws + (ib & 1) * 32 * WPITCH;
        bool scl = mode && (kb >= 128);
        #pragma unroll
        for (int ks = 0; ks < 4; ks++) {
            int kk = ks * 8;
            unsigned a[2][4];
            #pragma unroll
            for (int mt = 0; mt < 2; mt++) {
                int m = wm + mt * 16 + gid;
                float x0 = Xb[m * XPITCH + kk + tig];
                float x1 = Xb[(m + 8) * XPITCH + kk + tig];
                float x2 = Xb[m * XPITCH + kk + tig + 4];
                float x3 = Xb[(m + 8) * XPITCH + kk + tig + 4];
                if (scl) { x0 *= rcp0[mt]; x1 *= rcp1[mt]; x2 *= rcp0[mt]; x3 *= rcp1[mt]; }
                a[mt][0] = cvtu(x0); a[mt][1] = cvtu(x1);
                a[mt][2] = cvtu(x2); a[mt][3] = cvtu(x3);
            }
            #pragma unroll
            for (int nt = 0; nt < 8; nt++) {
                int n = wn + nt * 8 + gid;
                unsigned b0 = cvtu(Wb[(kk + tig) * WPITCH + n]);
                unsigned b1 = cvtu(Wb[(kk + tig + 4) * WPITCH + n]);
                mma8(c[0][nt], a[0], b0, b1);
                mma8(c[1][nt], a[1], b0, b1);
            }
        }
        __syncthreads();
    }

    #pragma unroll
    for (int nt = 0; nt < 8; nt++) {
        int col = wn + nt * 8 + tig * 2;
        float bz0 = bias[col], bz1 = bias[col + 1];
        #pragma unroll
        for (int mt = 0; mt < 2; mt++) {
            int row0 = rbase + wm + mt * 16 + gid;
            float4 cc = c[mt][nt];
            float o00 = cc.x + bz0, o01 = cc.y + bz1;
            float o10 = cc.z + bz0, o11 = cc.w + bz1;
            if (act) { o00 = ftanh(o00); o01 = ftanh(o01); o10 = ftanh(o10); o11 = ftanh(o11); }
            *(float2*)(Y + (size_t)row0 * ldy + col) = make_float2(o00, o01);
            *(float2*)(Y + (size_t)(row0 + 8) * ldy + col) = make_float2(o10, o11);
        }
    }
}

// ---------------- scatter both passes: vector atomics ----------------
__global__ void __launch_bounds__(256) k_scatter2(const int* __restrict__ e0,
        const int* __restrict__ e1, const float* __restrict__ Ma,
        const float* __restrict__ Mb, float* __restrict__ SUMa,
        float* __restrict__ SUMb, float* __restrict__ CNTa, float* __restrict__ CNTb) {
    int gw = (blockIdx.x * 256 + threadIdx.x) >> 5;
    int lane = threadIdx.x & 31;
    int pass = gw >> 19;
    int e = gw & 524287;
    int b = e >> 14;
    const int* eidx = pass ? e1 : e0;
    const float* m = pass ? Mb : Ma;
    float* sum = pass ? SUMb : SUMa;
    float* cnt = pass ? CNTb : CNTa;
    int2 ab = __ldg((const int2*)eidx + e);
    size_t basea = ((size_t)b * NNODE + ab.x) * 128;
    size_t baseb = ((size_t)b * NNODE + ab.y) * 128;
    float4 va = __ldg((const float4*)(m + basea) + lane);
    float4 vb = __ldg((const float4*)(m + baseb) + lane);
    red4(sum + basea + lane * 4, vb);
    red4(sum + baseb + lane * 4, va);
    if (lane == 0)      atomicAdd(cnt + b * NNODE + ab.x, 1.0f);
    else if (lane == 1) atomicAdd(cnt + b * NNODE + ab.y, 1.0f);
}

// ---------------- gate combine ----------------
__global__ void __launch_bounds__(256) k_gcomb(const float* __restrict__ GTa,
        const float* __restrict__ UTa, const float* __restrict__ GTb,
        const float* __restrict__ UTb, const float* __restrict__ h,
        float* __restrict__ hc) {
    int i = blockIdx.x * 256 + threadIdx.x;
    int pass = i >= 1048576;
    int j = pass ? i - 1048576 : i;
    int row = j >> 5, q = j & 31;
    const float* GT = pass ? GTb : GTa;
    const float* UT = pass ? UTb : UTa;
    float4 g = __ldg((const float4*)(GT + (size_t)row * 128) + q);
    float4 u = __ldg((const float4*)(UT + (size_t)row * 128) + q);
    float4 hv = __ldg((const float4*)(h + (size_t)row * 128) + q);
    float4 o;
    o.x = g.x * u.x + (1.0f - g.x) * hv.x;
    o.y = g.y * u.y + (1.0f - g.y) * hv.y;
    o.z = g.z * u.z + (1.0f - g.z) * hv.z;
    o.w = g.w * u.w + (1.0f - g.w) * hv.w;
    *(float4*)(hc + (size_t)row * 256 + pass * 128 + q * 4) = o;
}

// ---------------- fold W_in into Wq1/Wk1/Wv1 ----------------
__global__ void k_fuseW(const float* __restrict__ Wq1, const float* __restrict__ bq1,
                        const float* __restrict__ Wk1, const float* __restrict__ bk1,
                        const float* __restrict__ Wv1, const float* __restrict__ bv1,
                        const float* __restrict__ W_in, const float* __restrict__ b_in,
                        float* __restrict__ S) {
    int mat = blockIdx.y, r = blockIdx.x, c = threadIdx.x;
    const float* Wsrc = mat == 0 ? Wq1 : (mat == 1 ? Wk1 : Wv1);
    const float* bsrc = mat == 0 ? bq1 : (mat == 1 ? bk1 : bv1);
    float* Wd = S + (mat == 0 ? OFF_WQF : (mat == 1 ? OFF_WKF : OFF_WVF));
    float* bd = S + (mat == 0 ? OFF_BQF : (mat == 1 ? OFF_BKF : OFF_BVF));
    __shared__ float row[128];
    row[c] = (r < 256) ? Wsrc[r * 128 + c] : bsrc[c];
    __syncthreads();
    float a = 0.f;
    #pragma unroll 8
    for (int k = 0; k < 128; k++) a += row[k] * W_in[k * 384 + mat * 128 + c];
    if (r < 256) Wd[r * 128 + c] = a;
    else bd[c] = a + b_in[mat * 128 + c];
}

// ---------------- attention ----------------
__global__ void __launch_bounds__(512) k_attn(const float* __restrict__ q2,
        const float* __restrict__ k2, const float* __restrict__ v2,
        float* __restrict__ oh) {
    int h = blockIdx.x, b = blockIdx.y;
    __shared__ float Ks[256][17];
    __shared__ float Vs[256][17];
    int tid = threadIdx.x;
    for (int i = tid; i < 256 * 16; i += 512) {
        int k = i >> 4, d = i & 15;
        Ks[k][d] = k2[((size_t)b * 256 + k) * 128 + h * 16 + d];
        Vs[k][d] = v2[((size_t)b * 256 + k) * 128 + h * 16 + d];
    }
    __syncthreads();
    int warp = tid >> 5, lane = tid & 31;
    for (int q = warp; q < 1024; q += 16) {
        const float* qp = q2 + ((size_t)b * 1024 + q) * 128 + h * 16;
        float qv[16];
        #pragma unroll
        for (int d = 0; d < 16; d++) qv[d] = __ldg(qp + d);
        float s[8];
        #pragma unroll
        for (int j = 0; j < 8; j++) {
            int key = lane + 32 * j;
            float a = 0.f;
            #pragma unroll
            for (int d = 0; d < 16; d++) a += qv[d] * Ks[key][d];
            s[j] = a * 0.25f;
        }
        float mx = s[0];
        #pragma unroll
        for (int j = 1; j < 8; j++) mx = fmaxf(mx, s[j]);
        #pragma unroll
        for (int o = 16; o > 0; o >>= 1) mx = fmaxf(mx, __shfl_xor_sync(0xffffffffu, mx, o));
        float sm = 0.f;
        #pragma unroll
        for (int j = 0; j < 8; j++) { s[j] = __expf(s[j] - mx); sm += s[j]; }
        #pragma unroll
        for (int o = 16; o > 0; o >>= 1) sm += __shfl_xor_sync(0xffffffffu, sm, o);
        float inv = __fdividef(1.0f, sm);
        float acc[16];
        #pragma unroll
        for (int d = 0; d < 16; d++) acc[d] = 0.f;
        #pragma unroll
        for (int j = 0; j < 8; j++) {
            int key = lane + 32 * j;
            float p = s[j];
            #pragma unroll
            for (int d = 0; d < 16; d++) acc[d] += p * Vs[key][d];
        }
        #pragma unroll
        for (int d = 0; d < 16; d++) {
            #pragma unroll
            for (int o = 16; o > 0; o >>= 1) acc[d] += __shfl_xor_sync(0xffffffffu, acc[d], o);
            acc[d] *= inv;
        }
        if (lane == 0) {
            float* op = oh + ((size_t)b * 1024 + q) * 128 + h * 16;
            #pragma unroll
            for (int d = 0; d < 16; d++) op[d] = acc[d];
        }
    }
}

// ---------------- state_value + mask + stage ----------------
__global__ void k_final(const float* __restrict__ hnum, const float* __restrict__ hatt,
                        const float* __restrict__ stage, float* __restrict__ out) {
    int b = blockIdx.x, t = threadIdx.x;
    float* sv = out + 4194304 + (size_t)b * 258;
    __shared__ float part[256];
    {
        int c = t & 127, half = t >> 7;
        const float* p = hatt + (size_t)b * 131072 + (size_t)half * 512 * 128 + c;
        float s = 0.f;
        for (int n = 0; n < 512; n++) s += p[(size_t)n * 128];
        part[t] = s;
    }
    __syncthreads();
    if (t < 128) {
        sv[t] = hnum[b * 128 + t];
        sv[128 + t] = (part[t] + part[t + 128]) * (1.0f / 1024.0f);
    }
    if (t < 2) {
        sv[256 + t] = stage[b * 2 + t];
        out[4235328 + b * 2 + t] = stage[b * 2 + t];
    }
    for (int i = t; i < 1024; i += 256) out[4202560 + b * 1024 + i] = 1.0f;
}

extern "C" void kernel_launch(void* const* d_in, const int* in_sizes, int n_in,
                              void* d_out, int out_size) {
    const float* numerical = (const float*)d_in[0];
    const float* node_feature = (const float*)d_in[1];
    const float* stage = (const float*)d_in[2];
    const float* W_num0 = (const float*)d_in[3];
    const float* b_num0 = (const float*)d_in[4];
    const float* W_num1 = (const float*)d_in[5];
    const float* b_num1 = (const float*)d_in[6];
    const float* W_node = (const float*)d_in[7];
    const float* b_node = (const float*)d_in[8];
    const float* pos_enc = (const float*)d_in[9];
    const float* ew1 = (const float*)d_in[10];
    const float* eb1 = (const float*)d_in[11];
    const float* ew2 = (const float*)d_in[12];
    const float* eb2 = (const float*)d_in[13];
    const float* Wg = (const float*)d_in[14];
    const float* bg = (const float*)d_in[15];
    const float* Wu = (const float*)d_in[16];
    const float* bu = (const float*)d_in[17];
    const float* Wq1 = (const float*)d_in[18];
    const float* bq1 = (const float*)d_in[19];
    const float* Wk1 = (const float*)d_in[20];
    const float* bk1 = (const float*)d_in[21];
    const float* Wv1 = (const float*)d_in[22];
    const float* bv1 = (const float*)d_in[23];
    const float* W_in = (const float*)d_in[24];
    const float* b_in = (const float*)d_in[25];
    const float* W_out = (const float*)d_in[26];
    const float* b_out = (const float*)d_in[27];
    const int* e_dis = (const int*)d_in[28];
    const int* e_od = (const int*)d_in[29];
    const int* build_idx = (const int*)d_in[31];
    float* out = (float*)d_out;

    float* S = nullptr;
    cudaGetSymbolAddress((void**)&S, g_scratch);
    float* H    = S + OFF_H;
    float* T0a  = S + OFF_T0A;
    float* T0b  = S + OFF_T0B;
    float* Ma   = S + OFF_MA;
    float* Mb   = S + OFF_MB;
    float* SUMa = S + OFF_SUMA;
    float* SUMb = S + OFF_SUMB;
    float* CNTa = S + OFF_CNTA;
    float* CNTb = S + OFF_CNTB;
    float* GTa  = S + OFF_GTA;
    float* UTa  = S + OFF_UTA;
    float* GTb  = S + OFF_GTB;
    float* UTb  = S + OFF_UTB;
    float* HC   = S + OFF_HC;
    float* Q2   = S + OFF_Q2;
    float* K2   = S + OFF_K2;
    float* V2   = S + OFF_V2;
    float* OH   = S + OFF_OH;
    float* HNUM = S + OFF_HNUM;

    cudaFuncSetAttribute(gemm_tc, cudaFuncAttributeMaxDynamicSharedMemorySize,
                         GEMM_SMEM_BYTES);

    const int BIG = 1 << 30;

    k_hnum<<<32, 256>>>(numerical, W_num0, b_num0, W_num1, b_num1, HNUM);
    k_embed<<<4096, 128>>>(node_feature, W_node, b_node, pos_enc, H);
    k_fuseW<<<dim3(257, 3), 128>>>(Wq1, bq1, Wk1, bk1, Wv1, bv1, W_in, b_in, S);

    // edge-MLP layer 1 (only surviving L_GCN iteration), both passes batched
    {
        Jobs j = {};
        j.X[0] = H;   j.W[0] = ew1 + 2 * 16384; j.B[0] = eb1 + 2 * 128; j.Y[0] = T0a;
        j.X[1] = H;   j.W[1] = ew2 + 2 * 16384; j.B[1] = eb2 + 2 * 128; j.Y[1] = T0b;
        gemm_tc<<<dim3(256, 2), 256, GEMM_SMEM_BYTES>>>(j, 128, BIG, 0, nullptr, 128, 128, 1);
    }
    {
        Jobs j = {};
        j.X[0] = T0a; j.W[0] = ew1 + 3 * 16384; j.B[0] = eb1 + 3 * 128; j.Y[0] = Ma;
        j.X[1] = T0b; j.W[1] = ew2 + 3 * 16384; j.B[1] = eb2 + 3 * 128; j.Y[1] = Mb;
        gemm_tc<<<dim3(256, 2), 256, GEMM_SMEM_BYTES>>>(j, 128, BIG, 0, nullptr, 128, 128, 1);
    }

    cudaMemsetAsync(SUMa, 0, (2 * 4194304 + 2 * 32768) * sizeof(float));
    k_scatter2<<<131072, 256>>>(e_dis, e_od, Ma, Mb, SUMa, SUMb, CNTa, CNTb);

    // gate/update GEMMs, comb fused (K=256: k<128 from H, k>=128 from SUM*rcp)
    {
        Jobs j = {};
        j.X[0] = H; j.W[0] = Wg; j.B[0] = bg; j.Y[0] = GTa; j.SUM[0] = SUMa; j.CNT[0] = CNTa;
        j.X[1] = H; j.W[1] = Wu; j.B[1] = bu; j.Y[1] = UTa; j.SUM[1] = SUMa; j.CNT[1] = CNTa;
        j.X[2] = H; j.W[2] = Wg; j.B[2] = bg; j.Y[2] = GTb; j.SUM[2] = SUMb; j.CNT[2] = CNTb;
        j.X[3] = H; j.W[3] = Wu; j.B[3] = bu; j.Y[3] = UTb; j.SUM[3] = SUMb; j.CNT[3] = CNTb;
        gemm_tc<<<dim3(256, 4), 256, GEMM_SMEM_BYTES>>>(j, 128, BIG, 0, nullptr, 128, 256, 1);
    }
    k_gcomb<<<8192, 256>>>(GTa, UTa, GTb, UTb, H, HC);

    {
        Jobs j = {};
        j.X[0] = HC; j.W[0] = S + OFF_WQF; j.B[0] = S + OFF_BQF; j.Y[0] = Q2;
        gemm_tc<<<dim3(256, 1), 256, GEMM_SMEM_BYTES>>>(j, 256, BIG, 0, nullptr, 128, 256, 0);
    }
    {
        Jobs j = {};
        j.X[0] = HC; j.W[0] = S + OFF_WKF; j.B[0] = S + OFF_BKF; j.Y[0] = K2;
        j.X[1] = HC; j.W[1] = S + OFF_WVF; j.B[1] = S + OFF_BVF; j.Y[1] = V2;
        gemm_tc<<<dim3(64, 2), 256, GEMM_SMEM_BYTES>>>(j, 256, 256, 262144, build_idx, 128, 256, 0);
    }
    k_attn<<<dim3(8, 32), 512>>>(Q2, K2, V2, OH);
    {
        Jobs j = {};
        j.X[0] = OH; j.W[0] = W_out; j.B[0] = b_out; j.Y[0] = out;
        gemm_tc<<<dim3(256, 1), 256, GEMM_SMEM_BYTES>>>(j, 128, BIG, 0, nullptr, 128, 128, 0);
    }
    k_final<<<32, 256>>>(HNUM, out, stage, out);
}

// round 7
// speedup vs baseline: 2.2785x; 1.0043x over previous
#include <cuda_runtime.h>
#include <math.h>
#include <stdint.h>

#define NNODE 1024
#define EPS_F 1e-6f

// ---- scratch layout (floats) ----
#define OFF_H     ((size_t)0)
#define OFF_T0A   (OFF_H    + 4194304)
#define OFF_T0B   (OFF_T0A  + 4194304)
#define OFF_MA    (OFF_T0B  + 4194304)
#define OFF_MB    (OFF_MA   + 4194304)
#define OFF_SUMA  (OFF_MB   + 4194304)
#define OFF_SUMB  (OFF_SUMA + 4194304)
#define OFF_CNTA  (OFF_SUMB + 4194304)
#define OFF_CNTB  (OFF_CNTA + 32768)
#define OFF_GTA   (OFF_CNTB + 32768)
#define OFF_UTA   (OFF_GTA  + 4194304)
#define OFF_GTB   (OFF_UTA  + 4194304)
#define OFF_UTB   (OFF_GTB  + 4194304)
#define OFF_HC    (OFF_UTB  + 4194304)
#define OFF_Q2    (OFF_HC   + 8388608)
#define OFF_K2    (OFF_Q2   + 4194304)
#define OFF_V2    (OFF_K2   + 1048576)
#define OFF_OH    (OFF_V2   + 1048576)
#define OFF_HNUM  (OFF_OH   + 4194304)
#define OFF_WQF   (OFF_HNUM + 4096)
#define OFF_BQF   (OFF_WQF  + 32768)
#define OFF_WKF   (OFF_BQF  + 128)
#define OFF_BKF   (OFF_WKF  + 32768)
#define OFF_WVF   (OFF_BKF  + 128)
#define OFF_BVF   (OFF_WVF  + 32768)
#define OFF_PART  (OFF_BVF  + 128)
#define OFF_RE1A  (OFF_PART + 32768)
#define OFF_RE1B  (OFF_RE1A + 16384)
#define OFF_RE2A  (OFF_RE1B + 16384)
#define OFF_RE2B  (OFF_RE2A + 16384)
#define OFF_RWG   (OFF_RE2B + 16384)
#define OFF_RWU   (OFF_RWG  + 32768)
#define OFF_RWOUT (OFF_RWU  + 32768)
#define SCRATCH_FLOATS (OFF_RWOUT + 16384)

__device__ float g_scratch[SCRATCH_FLOATS];

__device__ __forceinline__ float ftanh(float x) {
    float t = __expf(2.0f * x);
    return 1.0f - __fdividef(2.0f, t + 1.0f);
}

__device__ __forceinline__ void red4(float* p, float4 v) {
    asm volatile("red.global.v4.f32.add [%0], {%1,%2,%3,%4};"
        :: "l"(p), "f"(v.x), "f"(v.y), "f"(v.z), "f"(v.w) : "memory");
}

__device__ __forceinline__ unsigned cvtu(float x) {
    unsigned u;
    asm("cvt.rna.tf32.f32 %0, %1;" : "=r"(u) : "f"(x));
    return u;
}

__device__ __forceinline__ float cvtf(float x) {
    return __uint_as_float(cvtu(x));
}

__device__ __forceinline__ void mma8(float4& c, const unsigned* a, unsigned b0, unsigned b1) {
    asm volatile("mma.sync.aligned.m16n8k8.row.col.f32.tf32.tf32.f32 "
        "{%0,%1,%2,%3}, {%4,%5,%6,%7}, {%8,%9}, {%0,%1,%2,%3};"
        : "+f"(c.x), "+f"(c.y), "+f"(c.z), "+f"(c.w)
        : "r"(a[0]), "r"(a[1]), "r"(a[2]), "r"(a[3]), "r"(b0), "r"(b1));
}

__device__ __forceinline__ void cpa16(void* s, const void* g) {
    unsigned sa = (unsigned)__cvta_generic_to_shared(s);
    asm volatile("cp.async.cg.shared.global [%0], [%1], 16;" :: "r"(sa), "l"(g));
}

// ---------------- weight pre-rounding (to canonical tf32) ----------------
struct RJobs {
    const float* src[7];
    float* dst[7];
    int n[7];
};
__global__ void k_roundW(RJobs j) {
    int job = blockIdx.y;
    int i = blockIdx.x * 256 + threadIdx.x;
    if (i < j.n[job]) j.dst[job][i] = cvtf(j.src[job][i]);
}

// ---------------- h_num ----------------
__global__ void k_hnum(const float* __restrict__ num, const float* __restrict__ W0,
                       const float* __restrict__ b0, const float* __restrict__ W1,
                       const float* __restrict__ b1, float* __restrict__ out) {
    __shared__ float xs[64];
    __shared__ float hid[256];
    int b = blockIdx.x, t = threadIdx.x;
    if (t < 64) xs[t] = num[b * 64 + t];
    __syncthreads();
    float a = b0[t];
    #pragma unroll 8
    for (int k = 0; k < 64; k++) a += xs[k] * W0[k * 256 + t];
    hid[t] = ftanh(a);
    __syncthreads();
    if (t < 128) {
        float a2 = b1[t];
        #pragma unroll 8
        for (int k = 0; k < 256; k++) a2 += hid[k] * W1[k * 128 + t];
        out[b * 128 + t] = ftanh(a2);
    }
}

// ---------------- node embed (output rounded to tf32) ----------------
__global__ void __launch_bounds__(128) k_embed(const float* __restrict__ nf,
        const float* __restrict__ Wn, const float* __restrict__ bn,
        const float* __restrict__ pos, float* __restrict__ h) {
    __shared__ float ws[4096];
    __shared__ float xs[256];
    int t = threadIdx.x;
    int rbase = blockIdx.x * 8;
    for (int i = t; i < 4096; i += 128) ws[i] = Wn[i];
    for (int i = t; i < 256; i += 128) xs[i] = nf[(size_t)rbase * 32 + i];
    __syncthreads();
    float bv = bn[t];
    #pragma unroll
    for (int r = 0; r < 8; r++) {
        float a = bv;
        #pragma unroll 8
        for (int k = 0; k < 32; k++) a += xs[r * 32 + k] * ws[k * 128 + t];
        int row = rbase + r;
        h[(size_t)row * 128 + t] = cvtf(ftanh(a) + pos[(size_t)(row & 1023) * 128 + t]);
    }
}

// ---------------- batched tf32 GEMM: 128x128 tile, cp.async double buffer ----------------
// act bit0 = tanh, bit1 = round output to tf32
// comb mode (SUM[j] != null): K=256, k<128 reads X (=h), k>=128 reads SUM*rcp (cvt at load)
struct Jobs {
    const float* X[4];
    const float* W[4];
    const float* B[4];
    float* Y[4];
    const float* SUM[4];
    const float* CNT[4];
};

#define XPITCH 36
#define WPITCH 132
#define SM_XB (2 * 128 * XPITCH)
#define SM_WB (2 * 32 * WPITCH)
#define GEMM_SMEM_BYTES ((SM_XB + SM_WB + 128 + 128) * 4)

__global__ void __launch_bounds__(256, 2) gemm_tc(Jobs jobs, int ldx, int rpb,
        size_t bstride, const int* __restrict__ rowmap, int ldy, int K, int act) {
    extern __shared__ float sm[];
    float* Xs = sm;
    float* Ws = sm + SM_XB;
    unsigned* rowoff = (unsigned*)(sm + SM_XB + SM_WB);
    float* rcps = (float*)(rowoff + 128);

    const float* __restrict__ X = jobs.X[blockIdx.y];
    const float* __restrict__ W = jobs.W[blockIdx.y];
    const float* __restrict__ bias = jobs.B[blockIdx.y];
    float* __restrict__ Y = jobs.Y[blockIdx.y];
    const float* __restrict__ SUM = jobs.SUM[blockIdx.y];
    const float* __restrict__ CNT = jobs.CNT[blockIdx.y];
    bool mode = (SUM != nullptr);

    int tid = threadIdx.x;
    int rbase = blockIdx.x * 128;
    if (tid < 128) {
        int r = rbase + tid;
        int bb = r / rpb;
        int n = r - bb * rpb;
        if (rowmap) n = rowmap[n];
        rowoff[tid] = (unsigned)((size_t)bb * bstride + (size_t)n * ldx);
        if (mode) rcps[tid] = __fdividef(1.0f, CNT[r] + EPS_F);
    }
    __syncthreads();

    int wid = tid >> 5, lane = tid & 31;
    int wm = (wid & 3) * 32;
    int wn = (wid >> 2) * 64;
    int gid = lane >> 2, tig = lane & 3;

    float4 c[2][8];
    #pragma unroll
    for (int i = 0; i < 2; i++)
        #pragma unroll
        for (int j = 0; j < 8; j++) c[i][j] = make_float4(0.f, 0.f, 0.f, 0.f);

    float rcp0[2], rcp1[2];
    #pragma unroll
    for (int mt = 0; mt < 2; mt++) {
        rcp0[mt] = mode ? rcps[wm + mt * 16 + gid] : 1.0f;
        rcp1[mt] = mode ? rcps[wm + mt * 16 + gid + 8] : 1.0f;
    }

    int nk = K >> 5;

    #define STAGE(IB) do { \
        int kb_ = (IB) * 32; \
        int buf_ = (IB) & 1; \
        const float* xb_ = X; int ko_ = kb_; \
        if (mode && kb_ >= 128) { xb_ = SUM; ko_ = kb_ - 128; } \
        _Pragma("unroll") \
        for (int p_ = 0; p_ < 4; p_++) { \
            int id_ = p_ * 256 + tid; \
            int r_ = id_ >> 3, c_ = (id_ & 7) * 4; \
            cpa16(&Xs[buf_ * 128 * XPITCH + r_ * XPITCH + c_], xb_ + rowoff[r_] + ko_ + c_); \
        } \
        _Pragma("unroll") \
        for (int p_ = 0; p_ < 4; p_++) { \
            int id_ = p_ * 256 + tid; \
            int k_ = id_ >> 5, c_ = (id_ & 31) * 4; \
            cpa16(&Ws[buf_ * 32 * WPITCH + k_ * WPITCH + c_], W + (size_t)(kb_ + k_) * 128 + c_); \
        } \
    } while (0)

    STAGE(0);
    asm volatile("cp.async.commit_group;");

    for (int ib = 0; ib < nk; ib++) {
        if (ib + 1 < nk) {
            STAGE(ib + 1);
            asm volatile("cp.async.commit_group;");
            asm volatile("cp.async.wait_group 1;");
        } else {
            asm volatile("cp.async.wait_group 0;");
        }
        __syncthreads();
        int kb = ib * 32;
        float* Xb = Xs + (ib & 1) * 128 * XPITCH;
        float* Wb = Ws + (ib & 1) * 32 * WPITCH;
        bool scl = mode && (kb >= 128);
        #pragma unroll
        for (int ks = 0; ks < 4; ks++) {
            int kk = ks * 8;
            unsigned a[2][4];
            #pragma unroll
            for (int mt = 0; mt < 2; mt++) {
                int m = wm + mt * 16 + gid;
                float x0 = Xb[m * XPITCH + kk + tig];
                float x1 = Xb[(m + 8) * XPITCH + kk + tig];
                float x2 = Xb[m * XPITCH + kk + tig + 4];
                float x3 = Xb[(m + 8) * XPITCH + kk + tig + 4];
                if (scl) {
                    a[mt][0] = cvtu(x0 * rcp0[mt]); a[mt][1] = cvtu(x1 * rcp1[mt]);
                    a[mt][2] = cvtu(x2 * rcp0[mt]); a[mt][3] = cvtu(x3 * rcp1[mt]);
                } else {
                    a[mt][0] = __float_as_uint(x0); a[mt][1] = __float_as_uint(x1);
                    a[mt][2] = __float_as_uint(x2); a[mt][3] = __float_as_uint(x3);
                }
            }
            #pragma unroll
            for (int nt = 0; nt < 8; nt++) {
                int n = wn + nt * 8 + gid;
                unsigned b0 = __float_as_uint(Wb[(kk + tig) * WPITCH + n]);
                unsigned b1 = __float_as_uint(Wb[(kk + tig + 4) * WPITCH + n]);
                mma8(c[0][nt], a[0], b0, b1);
                mma8(c[1][nt], a[1], b0, b1);
            }
        }
        __syncthreads();
    }

    #pragma unroll
    for (int nt = 0; nt < 8; nt++) {
        int col = wn + nt * 8 + tig * 2;
        float bz0 = bias[col], bz1 = bias[col + 1];
        #pragma unroll
        for (int mt = 0; mt < 2; mt++) {
            int row0 = rbase + wm + mt * 16 + gid;
            float4 cc = c[mt][nt];
            float o00 = cc.x + bz0, o01 = cc.y + bz1;
            float o10 = cc.z + bz0, o11 = cc.w + bz1;
            if (act & 1) { o00 = ftanh(o00); o01 = ftanh(o01); o10 = ftanh(o10); o11 = ftanh(o11); }
            if (act & 2) { o00 = cvtf(o00); o01 = cvtf(o01); o10 = cvtf(o10); o11 = cvtf(o11); }
            *(float2*)(Y + (size_t)row0 * ldy + col) = make_float2(o00, o01);
            *(float2*)(Y + (size_t)(row0 + 8) * ldy + col) = make_float2(o10, o11);
        }
    }
}

// ---------------- scatter both passes: vector atomics ----------------
__global__ void __launch_bounds__(256) k_scatter2(const int* __restrict__ e0,
        const int* __restrict__ e1, const float* __restrict__ Ma,
        const float* __restrict__ Mb, float* __restrict__ SUMa,
        float* __restrict__ SUMb, float* __restrict__ CNTa, float* __restrict__ CNTb) {
    int gw = (blockIdx.x * 256 + threadIdx.x) >> 5;
    int lane = threadIdx.x & 31;
    int pass = gw >> 19;
    int e = gw & 524287;
    int b = e >> 14;
    const int* eidx = pass ? e1 : e0;
    const float* m = pass ? Mb : Ma;
    float* sum = pass ? SUMb : SUMa;
    float* cnt = pass ? CNTb : CNTa;
    int2 ab = __ldg((const int2*)eidx + e);
    size_t basea = ((size_t)b * NNODE + ab.x) * 128;
    size_t baseb = ((size_t)b * NNODE + ab.y) * 128;
    float4 va = __ldg((const float4*)(m + basea) + lane);
    float4 vb = __ldg((const float4*)(m + baseb) + lane);
    red4(sum + basea + lane * 4, vb);
    red4(sum + baseb + lane * 4, va);
    if (lane == 0)      atomicAdd(cnt + b * NNODE + ab.x, 1.0f);
    else if (lane == 1) atomicAdd(cnt + b * NNODE + ab.y, 1.0f);
}

// ---------------- gate combine (output rounded for Q/K/V GEMMs) ----------------
__global__ void __launch_bounds__(256) k_gcomb(const float* __restrict__ GTa,
        const float* __restrict__ UTa, const float* __restrict__ GTb,
        const float* __restrict__ UTb, const float* __restrict__ h,
        float* __restrict__ hc) {
    int i = blockIdx.x * 256 + threadIdx.x;
    int pass = i >= 1048576;
    int j = pass ? i - 1048576 : i;
    int row = j >> 5, q = j & 31;
    const float* GT = pass ? GTb : GTa;
    const float* UT = pass ? UTb : UTa;
    float4 g = __ldg((const float4*)(GT + (size_t)row * 128) + q);
    float4 u = __ldg((const float4*)(UT + (size_t)row * 128) + q);
    float4 hv = __ldg((const float4*)(h + (size_t)row * 128) + q);
    float4 o;
    o.x = cvtf(g.x * u.x + (1.0f - g.x) * hv.x);
    o.y = cvtf(g.y * u.y + (1.0f - g.y) * hv.y);
    o.z = cvtf(g.z * u.z + (1.0f - g.z) * hv.z);
    o.w = cvtf(g.w * u.w + (1.0f - g.w) * hv.w);
    *(float4*)(hc + (size_t)row * 256 + pass * 128 + q * 4) = o;
}

// ---------------- fold W_in into Wq1/Wk1/Wv1 (rounded) ----------------
__global__ void k_fuseW(const float* __restrict__ Wq1, const float* __restrict__ bq1,
                        const float* __restrict__ Wk1, const float* __restrict__ bk1,
                        const float* __restrict__ Wv1, const float* __restrict__ bv1,
                        const float* __restrict__ W_in, const float* __restrict__ b_in,
                        float* __restrict__ S) {
    int mat = blockIdx.y, r = blockIdx.x, c = threadIdx.x;
    const float* Wsrc = mat == 0 ? Wq1 : (mat == 1 ? Wk1 : Wv1);
    const float* bsrc = mat == 0 ? bq1 : (mat == 1 ? bk1 : bv1);
    float* Wd = S + (mat == 0 ? OFF_WQF : (mat == 1 ? OFF_WKF : OFF_WVF));
    float* bd = S + (mat == 0 ? OFF_BQF : (mat == 1 ? OFF_BKF : OFF_BVF));
    __shared__ float row[128];
    row[c] = (r < 256) ? Wsrc[r * 128 + c] : bsrc[c];
    __syncthreads();
    float a = 0.f;
    #pragma unroll 8
    for (int k = 0; k < 128; k++) a += row[k] * W_in[k * 384 + mat * 128 + c];
    if (r < 256) Wd[r * 128 + c] = cvtf(a);
    else bd[c] = a + b_in[mat * 128 + c];
}

// ---------------- attention (output rounded for W_out GEMM) ----------------
__global__ void __launch_bounds__(512) k_attn(const float* __restrict__ q2,
        const float* __restrict__ k2, const float* __restrict__ v2,
        float* __restrict__ oh) {
    int h = blockIdx.x, b = blockIdx.y;
    __shared__ float Ks[256][17];
    __shared__ float Vs[256][17];
    int tid = threadIdx.x;
    for (int i = tid; i < 256 * 16; i += 512) {
        int k = i >> 4, d = i & 15;
        Ks[k][d] = k2[((size_t)b * 256 + k) * 128 + h * 16 + d];
        Vs[k][d] = v2[((size_t)b * 256 + k) * 128 + h * 16 + d];
    }
    __syncthreads();
    int warp = tid >> 5, lane = tid & 31;
    for (int q = warp; q < 1024; q += 16) {
        const float* qp = q2 + ((size_t)b * 1024 + q) * 128 + h * 16;
        float qv[16];
        #pragma unroll
        for (int d = 0; d < 16; d++) qv[d] = __ldg(qp + d);
        float s[8];
        #pragma unroll
        for (int j = 0; j < 8; j++) {
            int key = lane + 32 * j;
            float a = 0.f;
            #pragma unroll
            for (int d = 0; d < 16; d++) a += qv[d] * Ks[key][d];
            s[j] = a * 0.25f;
        }
        float mx = s[0];
        #pragma unroll
        for (int j = 1; j < 8; j++) mx = fmaxf(mx, s[j]);
        #pragma unroll
        for (int o = 16; o > 0; o >>= 1) mx = fmaxf(mx, __shfl_xor_sync(0xffffffffu, mx, o));
        float sm = 0.f;
        #pragma unroll
        for (int j = 0; j < 8; j++) { s[j] = __expf(s[j] - mx); sm += s[j]; }
        #pragma unroll
        for (int o = 16; o > 0; o >>= 1) sm += __shfl_xor_sync(0xffffffffu, sm, o);
        float inv = __fdividef(1.0f, sm);
        float acc[16];
        #pragma unroll
        for (int d = 0; d < 16; d++) acc[d] = 0.f;
        #pragma unroll
        for (int j = 0; j < 8; j++) {
            int key = lane + 32 * j;
            float p = s[j];
            #pragma unroll
            for (int d = 0; d < 16; d++) acc[d] += p * Vs[key][d];
        }
        #pragma unroll
        for (int d = 0; d < 16; d++) {
            #pragma unroll
            for (int o = 16; o > 0; o >>= 1) acc[d] += __shfl_xor_sync(0xffffffffu, acc[d], o);
            acc[d] *= inv;
        }
        if (lane == 0) {
            float* op = oh + ((size_t)b * 1024 + q) * 128 + h * 16;
            #pragma unroll
            for (int d = 0; d < 16; d++) op[d] = cvtf(acc[d]);
        }
    }
}

// ---------------- mean partials (256 CTAs) ----------------
__global__ void __launch_bounds__(128) k_fpart(const float* __restrict__ hatt,
        float* __restrict__ part) {
    int b = blockIdx.x, ch = blockIdx.y, t = threadIdx.x;
    const float* p = hatt + (size_t)b * 131072 + (size_t)ch * 128 * 128 + t;
    float s = 0.f;
    #pragma unroll 8
    for (int n = 0; n < 128; n++) s += p[(size_t)n * 128];
    part[(b * 8 + ch) * 128 + t] = s;
}

// ---------------- state_value + mask + stage ----------------
__global__ void k_final2(const float* __restrict__ hnum, const float* __restrict__ part,
                         const float* __restrict__ stage, float* __restrict__ out) {
    int b = blockIdx.x, t = threadIdx.x;
    float* sv = out + 4194304 + (size_t)b * 258;
    if (t < 128) {
        sv[t] = hnum[b * 128 + t];
        float s = 0.f;
        #pragma unroll
        for (int c = 0; c < 8; c++) s += part[(b * 8 + c) * 128 + t];
        sv[128 + t] = s * (1.0f / 1024.0f);
    }
    if (t < 2) {
        sv[256 + t] = stage[b * 2 + t];
        out[4235328 + b * 2 + t] = stage[b * 2 + t];
    }
    for (int i = t; i < 1024; i += 256) out[4202560 + b * 1024 + i] = 1.0f;
}

extern "C" void kernel_launch(void* const* d_in, const int* in_sizes, int n_in,
                              void* d_out, int out_size) {
    const float* numerical = (const float*)d_in[0];
    const float* node_feature = (const float*)d_in[1];
    const float* stage = (const float*)d_in[2];
    const float* W_num0 = (const float*)d_in[3];
    const float* b_num0 = (const float*)d_in[4];
    const float* W_num1 = (const float*)d_in[5];
    const float* b_num1 = (const float*)d_in[6];
    const float* W_node = (const float*)d_in[7];
    const float* b_node = (const float*)d_in[8];
    const float* pos_enc = (const float*)d_in[9];
    const float* ew1 = (const float*)d_in[10];
    const float* eb1 = (const float*)d_in[11];
    const float* ew2 = (const float*)d_in[12];
    const float* eb2 = (const float*)d_in[13];
    const float* Wg = (const float*)d_in[14];
    const float* bg = (const float*)d_in[15];
    const float* Wu = (const float*)d_in[16];
    const float* bu = (const float*)d_in[17];
    const float* Wq1 = (const float*)d_in[18];
    const float* bq1 = (const float*)d_in[19];
    const float* Wk1 = (const float*)d_in[20];
    const float* bk1 = (const float*)d_in[21];
    const float* Wv1 = (const float*)d_in[22];
    const float* bv1 = (const float*)d_in[23];
    const float* W_in = (const float*)d_in[24];
    const float* b_in = (const float*)d_in[25];
    const float* W_out = (const float*)d_in[26];
    const float* b_out = (const float*)d_in[27];
    const int* e_dis = (const int*)d_in[28];
    const int* e_od = (const int*)d_in[29];
    const int* build_idx = (const int*)d_in[31];
    float* out = (float*)d_out;

    float* S = nullptr;
    cudaGetSymbolAddress((void**)&S, g_scratch);
    float* H    = S + OFF_H;
    float* T0a  = S + OFF_T0A;
    float* T0b  = S + OFF_T0B;
    float* Ma   = S + OFF_MA;
    float* Mb   = S + OFF_MB;
    float* SUMa = S + OFF_SUMA;
    float* SUMb = S + OFF_SUMB;
    float* CNTa = S + OFF_CNTA;
    float* CNTb = S + OFF_CNTB;
    float* GTa  = S + OFF_GTA;
    float* UTa  = S + OFF_UTA;
    float* GTb  = S + OFF_GTB;
    float* UTb  = S + OFF_UTB;
    float* HC   = S + OFF_HC;
    float* Q2   = S + OFF_Q2;
    float* K2   = S + OFF_K2;
    float* V2   = S + OFF_V2;
    float* OH   = S + OFF_OH;
    float* HNUM = S + OFF_HNUM;
    float* PART = S + OFF_PART;

    cudaFuncSetAttribute(gemm_tc, cudaFuncAttributeMaxDynamicSharedMemorySize,
                         GEMM_SMEM_BYTES);

    const int BIG = 1 << 30;

    // pre-round weights to canonical tf32
    {
        RJobs rj = {};
        rj.src[0] = ew1 + 2 * 16384; rj.dst[0] = S + OFF_RE1A; rj.n[0] = 16384;
        rj.src[1] = ew1 + 3 * 16384; rj.dst[1] = S + OFF_RE1B; rj.n[1] = 16384;
        rj.src[2] = ew2 + 2 * 16384; rj.dst[2] = S + OFF_RE2A; rj.n[2] = 16384;
        rj.src[3] = ew2 + 3 * 16384; rj.dst[3] = S + OFF_RE2B; rj.n[3] = 16384;
        rj.src[4] = Wg;              rj.dst[4] = S + OFF_RWG;  rj.n[4] = 32768;
        rj.src[5] = Wu;              rj.dst[5] = S + OFF_RWU;  rj.n[5] = 32768;
        rj.src[6] = W_out;           rj.dst[6] = S + OFF_RWOUT; rj.n[6] = 16384;
        k_roundW<<<dim3(128, 7), 256>>>(rj);
    }

    k_hnum<<<32, 256>>>(numerical, W_num0, b_num0, W_num1, b_num1, HNUM);
    k_embed<<<4096, 128>>>(node_feature, W_node, b_node, pos_enc, H);
    k_fuseW<<<dim3(257, 3), 128>>>(Wq1, bq1, Wk1, bk1, Wv1, bv1, W_in, b_in, S);

    // edge-MLP layer 1 (only surviving L_GCN iteration), both passes batched
    {
        Jobs j = {};
        j.X[0] = H;   j.W[0] = S + OFF_RE1A; j.B[0] = eb1 + 2 * 128; j.Y[0] = T0a;
        j.X[1] = H;   j.W[1] = S + OFF_RE2A; j.B[1] = eb2 + 2 * 128; j.Y[1] = T0b;
        gemm_tc<<<dim3(256, 2), 256, GEMM_SMEM_BYTES>>>(j, 128, BIG, 0, nullptr, 128, 128, 3);
    }
    {
        Jobs j = {};
        j.X[0] = T0a; j.W[0] = S + OFF_RE1B; j.B[0] = eb1 + 3 * 128; j.Y[0] = Ma;
        j.X[1] = T0b; j.W[1] = S + OFF_RE2B; j.B[1] = eb2 + 3 * 128; j.Y[1] = Mb;
        gemm_tc<<<dim3(256, 2), 256, GEMM_SMEM_BYTES>>>(j, 128, BIG, 0, nullptr, 128, 128, 1);
    }

    cudaMemsetAsync(SUMa, 0, (2 * 4194304 + 2 * 32768) * sizeof(float));
    k_scatter2<<<131072, 256>>>(e_dis, e_od, Ma, Mb, SUMa, SUMb, CNTa, CNTb);

    // gate/update GEMMs, comb fused (K=256: k<128 from H, k>=128 from SUM*rcp)
    {
        Jobs j = {};
        j.X[0] = H; j.W[0] = S + OFF_RWG; j.B[0] = bg; j.Y[0] = GTa; j.SUM[0] = SUMa; j.CNT[0] = CNTa;
        j.X[1] = H; j.W[1] = S + OFF_RWU; j.B[1] = bu; j.Y[1] = UTa; j.SUM[1] = SUMa; j.CNT[1] = CNTa;
        j.X[2] = H; j.W[2] = S + OFF_RWG; j.B[2] = bg; j.Y[2] = GTb; j.SUM[2] = SUMb; j.CNT[2] = CNTb;
        j.X[3] = H; j.W[3] = S + OFF_RWU; j.B[3] = bu; j.Y[3] = UTb; j.SUM[3] = SUMb; j.CNT[3] = CNTb;
        gemm_tc<<<dim3(256, 4), 256, GEMM_SMEM_BYTES>>>(j, 128, BIG, 0, nullptr, 128, 256, 1);
    }
    k_gcomb<<<8192, 256>>>(GTa, UTa, GTb, UTb, H, HC);

    {
        Jobs j = {};
        j.X[0] = HC; j.W[0] = S + OFF_WQF; j.B[0] = S + OFF_BQF; j.Y[0] = Q2;
        gemm_tc<<<dim3(256, 1), 256, GEMM_SMEM_BYTES>>>(j, 256, BIG, 0, nullptr, 128, 256, 0);
    }
    {
        Jobs j = {};
        j.X[0] = HC; j.W[0] = S + OFF_WKF; j.B[0] = S + OFF_BKF; j.Y[0] = K2;
        j.X[1] = HC; j.W[1] = S + OFF_WVF; j.B[1] = S + OFF_BVF; j.Y[1] = V2;
        gemm_tc<<<dim3(64, 2), 256, GEMM_SMEM_BYTES>>>(j, 256, 256, 262144, build_idx, 128, 256, 0);
    }
    k_attn<<<dim3(8, 32), 512>>>(Q2, K2, V2, OH);
    {
        Jobs j = {};
        j.X[0] = OH; j.W[0] = S + OFF_RWOUT; j.B[0] = b_out; j.Y[0] = out;
        gemm_tc<<<dim3(256, 1), 256, GEMM_SMEM_BYTES>>>(j, 128, BIG, 0, nullptr, 128, 128, 0);
    }
    k_fpart<<<dim3(32, 8), 128>>>(out, PART);
    k_final2<<<32, 256>>>(HNUM, PART, stage, out);
}

// round 8
// speedup vs baseline: 2.7467x; 1.2055x over previous
#include <cuda_runtime.h>
#include <math.h>
#include <stdint.h>

#define NNODE 1024
#define EPS_F 1e-6f

// ---- scratch layout (floats) ----
#define OFF_H     ((size_t)0)
#define OFF_T0A   (OFF_H    + 4194304)
#define OFF_T0B   (OFF_T0A  + 4194304)
#define OFF_MA    (OFF_T0B  + 4194304)
#define OFF_MB    (OFF_MA   + 4194304)
#define OFF_AVGA  (OFF_MB   + 4194304)
#define OFF_AVGB  (OFF_AVGA + 4194304)
#define OFF_ADJA  (OFF_AVGB + 4194304)
#define OFF_ADJB  (OFF_ADJA + 4194304)
#define OFF_CNTIA (OFF_ADJB + 4194304)
#define OFF_CNTIB (OFF_CNTIA + 32768)
#define OFF_GTA   (OFF_CNTIB + 32768)
#define OFF_UTA   (OFF_GTA  + 4194304)
#define OFF_GTB   (OFF_UTA  + 4194304)
#define OFF_UTB   (OFF_GTB  + 4194304)
#define OFF_HC    (OFF_UTB  + 4194304)
#define OFF_Q2    (OFF_HC   + 8388608)
#define OFF_K2    (OFF_Q2   + 4194304)
#define OFF_V2    (OFF_K2   + 1048576)
#define OFF_OH    (OFF_V2   + 1048576)
#define OFF_HNUM  (OFF_OH   + 4194304)
#define OFF_WQF   (OFF_HNUM + 4096)
#define OFF_BQF   (OFF_WQF  + 32768)
#define OFF_WKF   (OFF_BQF  + 128)
#define OFF_BKF   (OFF_WKF  + 32768)
#define OFF_WVF   (OFF_BKF  + 128)
#define OFF_BVF   (OFF_WVF  + 32768)
#define OFF_PART  (OFF_BVF  + 128)
#define OFF_RE1A  (OFF_PART + 32768)
#define OFF_RE1B  (OFF_RE1A + 16384)
#define OFF_RE2A  (OFF_RE1B + 16384)
#define OFF_RE2B  (OFF_RE2A + 16384)
#define OFF_RWG   (OFF_RE2B + 16384)
#define OFF_RWU   (OFF_RWG  + 32768)
#define OFF_RWOUT (OFF_RWU  + 32768)
#define SCRATCH_FLOATS (OFF_RWOUT + 16384)

__device__ float g_scratch[SCRATCH_FLOATS];

__device__ __forceinline__ float ftanh(float x) {
    float t = __expf(2.0f * x);
    return 1.0f - __fdividef(2.0f, t + 1.0f);
}

__device__ __forceinline__ unsigned cvtu(float x) {
    unsigned u;
    asm("cvt.rna.tf32.f32 %0, %1;" : "=r"(u) : "f"(x));
    return u;
}

__device__ __forceinline__ float cvtf(float x) {
    return __uint_as_float(cvtu(x));
}

__device__ __forceinline__ void mma8(float4& c, const unsigned* a, unsigned b0, unsigned b1) {
    asm volatile("mma.sync.aligned.m16n8k8.row.col.f32.tf32.tf32.f32 "
        "{%0,%1,%2,%3}, {%4,%5,%6,%7}, {%8,%9}, {%0,%1,%2,%3};"
        : "+f"(c.x), "+f"(c.y), "+f"(c.z), "+f"(c.w)
        : "r"(a[0]), "r"(a[1]), "r"(a[2]), "r"(a[3]), "r"(b0), "r"(b1));
}

__device__ __forceinline__ void cpa16(void* s, const void* g) {
    unsigned sa = (unsigned)__cvta_generic_to_shared(s);
    asm volatile("cp.async.cg.shared.global [%0], [%1], 16;" :: "r"(sa), "l"(g));
}

// ---------------- weight pre-rounding (to canonical tf32) ----------------
struct RJobs {
    const float* src[7];
    float* dst[7];
    int n[7];
};
__global__ void k_roundW(RJobs j) {
    int job = blockIdx.y;
    int i = blockIdx.x * 256 + threadIdx.x;
    if (i < j.n[job]) j.dst[job][i] = cvtf(j.src[job][i]);
}

// ---------------- h_num ----------------
__global__ void k_hnum(const float* __restrict__ num, const float* __restrict__ W0,
                       const float* __restrict__ b0, const float* __restrict__ W1,
                       const float* __restrict__ b1, float* __restrict__ out) {
    __shared__ float xs[64];
    __shared__ float hid[256];
    int b = blockIdx.x, t = threadIdx.x;
    if (t < 64) xs[t] = num[b * 64 + t];
    __syncthreads();
    float a = b0[t];
    #pragma unroll 8
    for (int k = 0; k < 64; k++) a += xs[k] * W0[k * 256 + t];
    hid[t] = ftanh(a);
    __syncthreads();
    if (t < 128) {
        float a2 = b1[t];
        #pragma unroll 8
        for (int k = 0; k < 256; k++) a2 += hid[k] * W1[k * 128 + t];
        out[b * 128 + t] = ftanh(a2);
    }
}

// ---------------- node embed (output rounded to tf32) ----------------
__global__ void __launch_bounds__(128) k_embed(const float* __restrict__ nf,
        const float* __restrict__ Wn, const float* __restrict__ bn,
        const float* __restrict__ pos, float* __restrict__ h) {
    __shared__ float ws[4096];
    __shared__ float xs[256];
    int t = threadIdx.x;
    int rbase = blockIdx.x * 8;
    for (int i = t; i < 4096; i += 128) ws[i] = Wn[i];
    for (int i = t; i < 256; i += 128) xs[i] = nf[(size_t)rbase * 32 + i];
    __syncthreads();
    float bv = bn[t];
    #pragma unroll
    for (int r = 0; r < 8; r++) {
        float a = bv;
        #pragma unroll 8
        for (int k = 0; k < 32; k++) a += xs[r * 32 + k] * ws[k * 128 + t];
        int row = rbase + r;
        h[(size_t)row * 128 + t] = cvtf(ftanh(a) + pos[(size_t)(row & 1023) * 128 + t]);
    }
}

// ---------------- batched tf32 GEMM: 128x128 tile, cp.async double buffer ----------------
// act bit0 = tanh, bit1 = round output to tf32
// comb mode (SUM[j] != null): K=256, k<128 reads X (=h), k>=128 reads SUM (pre-scaled AVG)
struct Jobs {
    const float* X[4];
    const float* W[4];
    const float* B[4];
    float* Y[4];
    const float* SUM[4];
};

#define XPITCH 36
#define WPITCH 132
#define SM_XB (2 * 128 * XPITCH)
#define SM_WB (2 * 32 * WPITCH)
#define GEMM_SMEM_BYTES ((SM_XB + SM_WB + 128) * 4)

__global__ void __launch_bounds__(256, 2) gemm_tc(Jobs jobs, int ldx, int rpb,
        size_t bstride, const int* __restrict__ rowmap, int ldy, int K, int act) {
    extern __shared__ float sm[];
    float* Xs = sm;
    float* Ws = sm + SM_XB;
    unsigned* rowoff = (unsigned*)(sm + SM_XB + SM_WB);

    const float* __restrict__ X = jobs.X[blockIdx.y];
    const float* __restrict__ W = jobs.W[blockIdx.y];
    const float* __restrict__ bias = jobs.B[blockIdx.y];
    float* __restrict__ Y = jobs.Y[blockIdx.y];
    const float* __restrict__ SUM = jobs.SUM[blockIdx.y];
    bool mode = (SUM != nullptr);

    int tid = threadIdx.x;
    int rbase = blockIdx.x * 128;
    if (tid < 128) {
        int r = rbase + tid;
        int bb = r / rpb;
        int n = r - bb * rpb;
        if (rowmap) n = rowmap[n];
        rowoff[tid] = (unsigned)((size_t)bb * bstride + (size_t)n * ldx);
    }
    __syncthreads();

    int wid = tid >> 5, lane = tid & 31;
    int wm = (wid & 3) * 32;
    int wn = (wid >> 2) * 64;
    int gid = lane >> 2, tig = lane & 3;

    float4 c[2][8];
    #pragma unroll
    for (int i = 0; i < 2; i++)
        #pragma unroll
        for (int j = 0; j < 8; j++) c[i][j] = make_float4(0.f, 0.f, 0.f, 0.f);

    int nk = K >> 5;

    #define STAGE(IB) do { \
        int kb_ = (IB) * 32; \
        int buf_ = (IB) & 1; \
        const float* xb_ = X; int ko_ = kb_; \
        if (mode && kb_ >= 128) { xb_ = SUM; ko_ = kb_ - 128; } \
        _Pragma("unroll") \
        for (int p_ = 0; p_ < 4; p_++) { \
            int id_ = p_ * 256 + tid; \
            int r_ = id_ >> 3, c_ = (id_ & 7) * 4; \
            cpa16(&Xs[buf_ * 128 * XPITCH + r_ * XPITCH + c_], xb_ + rowoff[r_] + ko_ + c_); \
        } \
        _Pragma("unroll") \
        for (int p_ = 0; p_ < 4; p_++) { \
            int id_ = p_ * 256 + tid; \
            int k_ = id_ >> 5, c_ = (id_ & 31) * 4; \
            cpa16(&Ws[buf_ * 32 * WPITCH + k_ * WPITCH + c_], W + (size_t)(kb_ + k_) * 128 + c_); \
        } \
    } while (0)

    STAGE(0);
    asm volatile("cp.async.commit_group;");

    for (int ib = 0; ib < nk; ib++) {
        if (ib + 1 < nk) {
            STAGE(ib + 1);
            asm volatile("cp.async.commit_group;");
            asm volatile("cp.async.wait_group 1;");
        } else {
            asm volatile("cp.async.wait_group 0;");
        }
        __syncthreads();
        float* Xb = Xs + (ib & 1) * 128 * XPITCH;
        float* Wb = Ws + (ib & 1) * 32 * WPITCH;
        #pragma unroll
        for (int ks = 0; ks < 4; ks++) {
            int kk = ks * 8;
            unsigned a[2][4];
            #pragma unroll
            for (int mt = 0; mt < 2; mt++) {
                int m = wm + mt * 16 + gid;
                a[mt][0] = __float_as_uint(Xb[m * XPITCH + kk + tig]);
                a[mt][1] = __float_as_uint(Xb[(m + 8) * XPITCH + kk + tig]);
                a[mt][2] = __float_as_uint(Xb[m * XPITCH + kk + tig + 4]);
                a[mt][3] = __float_as_uint(Xb[(m + 8) * XPITCH + kk + tig + 4]);
            }
            #pragma unroll
            for (int nt = 0; nt < 8; nt++) {
                int n = wn + nt * 8 + gid;
                unsigned b0 = __float_as_uint(Wb[(kk + tig) * WPITCH + n]);
                unsigned b1 = __float_as_uint(Wb[(kk + tig + 4) * WPITCH + n]);
                mma8(c[0][nt], a[0], b0, b1);
                mma8(c[1][nt], a[1], b0, b1);
            }
        }
        __syncthreads();
    }

    #pragma unroll
    for (int nt = 0; nt < 8; nt++) {
        int col = wn + nt * 8 + tig * 2;
        float bz0 = bias[col], bz1 = bias[col + 1];
        #pragma unroll
        for (int mt = 0; mt < 2; mt++) {
            int row0 = rbase + wm + mt * 16 + gid;
            float4 cc = c[mt][nt];
            float o00 = cc.x + bz0, o01 = cc.y + bz1;
            float o10 = cc.z + bz0, o11 = cc.w + bz1;
            if (act & 1) { o00 = ftanh(o00); o01 = ftanh(o01); o10 = ftanh(o10); o11 = ftanh(o11); }
            if (act & 2) { o00 = cvtf(o00); o01 = cvtf(o01); o10 = cvtf(o10); o11 = cvtf(o11); }
            *(float2*)(Y + (size_t)row0 * ldy + col) = make_float2(o00, o01);
            *(float2*)(Y + (size_t)(row0 + 8) * ldy + col) = make_float2(o10, o11);
        }
    }
}

// ---------------- adjacency build: one thread per edge ----------------
__global__ void __launch_bounds__(256) k_build(const int* __restrict__ e0,
        const int* __restrict__ e1, int* __restrict__ adjA, int* __restrict__ cntA,
        int* __restrict__ adjB, int* __restrict__ cntB) {
    int i = blockIdx.x * 256 + threadIdx.x;      // 0..1048575
    int pass = i >= 524288;
    int e = pass ? i - 524288 : i;
    const int* eidx = pass ? e1 : e0;
    int* adj = pass ? adjB : adjA;
    int* cnt = pass ? cntB : cntA;
    int b = e >> 14;
    int2 ab = __ldg((const int2*)eidx + e);
    int na = b * NNODE + ab.x;
    int nb = b * NNODE + ab.y;
    int p = atomicAdd(&cnt[na], 1);
    if (p < 128) adj[na * 128 + p] = nb;
    int q = atomicAdd(&cnt[nb], 1);
    if (q < 128) adj[nb * 128 + q] = na;
}

// ---------------- gather: one warp per (node, pass); AVG = cvtf(sum * rcp) ----------------
__global__ void __launch_bounds__(256) k_gather(const int* __restrict__ adjA,
        const int* __restrict__ cntA, const int* __restrict__ adjB,
        const int* __restrict__ cntB, const float* __restrict__ Ma,
        const float* __restrict__ Mb, float* __restrict__ AVGa, float* __restrict__ AVGb) {
    int gw = (blockIdx.x * 256 + threadIdx.x) >> 5;
    int lane = threadIdx.x & 31;
    int pass = gw >= 32768;
    int row = gw & 32767;
    const int* adj = (pass ? adjB : adjA) + row * 128;
    int cnt = (pass ? cntB : cntA)[row];
    const float* m = pass ? Mb : Ma;
    float* avg = pass ? AVGb : AVGa;
    int n = min(cnt, 128);
    float4 acc = make_float4(0.f, 0.f, 0.f, 0.f);
    int i = 0;
    for (; i + 4 <= n; i += 4) {
        int4 nb = *(const int4*)(adj + i);
        float4 v0 = __ldg((const float4*)(m + (size_t)nb.x * 128) + lane);
        float4 v1 = __ldg((const float4*)(m + (size_t)nb.y * 128) + lane);
        float4 v2 = __ldg((const float4*)(m + (size_t)nb.z * 128) + lane);
        float4 v3 = __ldg((const float4*)(m + (size_t)nb.w * 128) + lane);
        acc.x += v0.x + v1.x + v2.x + v3.x;
        acc.y += v0.y + v1.y + v2.y + v3.y;
        acc.z += v0.z + v1.z + v2.z + v3.z;
        acc.w += v0.w + v1.w + v2.w + v3.w;
    }
    for (; i < n; i++) {
        int nb = adj[i];
        float4 v = __ldg((const float4*)(m + (size_t)nb * 128) + lane);
        acc.x += v.x; acc.y += v.y; acc.z += v.z; acc.w += v.w;
    }
    float rcp = __fdividef(1.0f, (float)cnt + EPS_F);
    float4 o;
    o.x = cvtf(acc.x * rcp); o.y = cvtf(acc.y * rcp);
    o.z = cvtf(acc.z * rcp); o.w = cvtf(acc.w * rcp);
    *(float4*)(avg + (size_t)row * 128 + lane * 4) = o;
}

// ---------------- gate combine (output rounded for Q/K/V GEMMs) ----------------
__global__ void __launch_bounds__(256) k_gcomb(const float* __restrict__ GTa,
        const float* __restrict__ UTa, const float* __restrict__ GTb,
        const float* __restrict__ UTb, const float* __restrict__ h,
        float* __restrict__ hc) {
    int i = blockIdx.x * 256 + threadIdx.x;
    int pass = i >= 1048576;
    int j = pass ? i - 1048576 : i;
    int row = j >> 5, q = j & 31;
    const float* GT = pass ? GTb : GTa;
    const float* UT = pass ? UTb : UTa;
    float4 g = __ldg((const float4*)(GT + (size_t)row * 128) + q);
    float4 u = __ldg((const float4*)(UT + (size_t)row * 128) + q);
    float4 hv = __ldg((const float4*)(h + (size_t)row * 128) + q);
    float4 o;
    o.x = cvtf(g.x * u.x + (1.0f - g.x) * hv.x);
    o.y = cvtf(g.y * u.y + (1.0f - g.y) * hv.y);
    o.z = cvtf(g.z * u.z + (1.0f - g.z) * hv.z);
    o.w = cvtf(g.w * u.w + (1.0f - g.w) * hv.w);
    *(float4*)(hc + (size_t)row * 256 + pass * 128 + q * 4) = o;
}

// ---------------- fold W_in into Wq1/Wk1/Wv1 (tiled, coalesced) ----------------
__global__ void __launch_bounds__(128) k_fuseW2(const float* __restrict__ Wq1,
        const float* __restrict__ bq1, const float* __restrict__ Wk1,
        const float* __restrict__ bk1, const float* __restrict__ Wv1,
        const float* __restrict__ bv1, const float* __restrict__ W_in,
        const float* __restrict__ b_in, float* __restrict__ S) {
    int mat = blockIdx.x;     // 0..2
    int rb = blockIdx.y;      // 0..8 (8 = bias row)
    int c = threadIdx.x;
    const float* Wsrc = mat == 0 ? Wq1 : (mat == 1 ? Wk1 : Wv1);
    const float* bsrc = mat == 0 ? bq1 : (mat == 1 ? bk1 : bv1);
    float* Wd = S + (mat == 0 ? OFF_WQF : (mat == 1 ? OFF_WKF : OFF_WVF));
    float* bd = S + (mat == 0 ? OFF_BQF : (mat == 1 ? OFF_BKF : OFF_BVF));
    if (rb == 8) {
        __shared__ float bs[128];
        bs[c] = bsrc[c];
        __syncthreads();
        float a = 0.f;
        #pragma unroll 8
        for (int k = 0; k < 128; k++) a += bs[k] * W_in[k * 384 + mat * 128 + c];
        bd[c] = a + b_in[mat * 128 + c];
        return;
    }
    __shared__ float Win[16][128];
    __shared__ float Xs[32][17];
    int r0 = rb * 32;
    float acc[32];
    #pragma unroll
    for (int r = 0; r < 32; r++) acc[r] = 0.f;
    for (int kb = 0; kb < 128; kb += 16) {
        __syncthreads();
        #pragma unroll
        for (int k = 0; k < 16; k++) Win[k][c] = W_in[(kb + k) * 384 + mat * 128 + c];
        #pragma unroll
        for (int p = 0; p < 4; p++) {
            int idx = p * 128 + c;
            int r = idx >> 4, k = idx & 15;
            Xs[r][k] = Wsrc[(r0 + r) * 128 + kb + k];
        }
        __syncthreads();
        #pragma unroll
        for (int k = 0; k < 16; k++) {
            float w = Win[k][c];
            #pragma unroll
            for (int r = 0; r < 32; r++) acc[r] += Xs[r][k] * w;
        }
    }
    #pragma unroll
    for (int r = 0; r < 32; r++) Wd[(r0 + r) * 128 + c] = cvtf(acc[r]);
}

// ---------------- attention (output rounded for W_out GEMM) ----------------
__global__ void __launch_bounds__(512) k_attn(const float* __restrict__ q2,
        const float* __restrict__ k2, const float* __restrict__ v2,
        float* __restrict__ oh) {
    int h = blockIdx.x, b = blockIdx.y;
    __shared__ float Ks[256][17];
    __shared__ float Vs[256][17];
    int tid = threadIdx.x;
    for (int i = tid; i < 256 * 16; i += 512) {
        int k = i >> 4, d = i & 15;
        Ks[k][d] = k2[((size_t)b * 256 + k) * 128 + h * 16 + d];
        Vs[k][d] = v2[((size_t)b * 256 + k) * 128 + h * 16 + d];
    }
    __syncthreads();
    int warp = tid >> 5, lane = tid & 31;
    for (int q = warp; q < 1024; q += 16) {
        const float* qp = q2 + ((size_t)b * 1024 + q) * 128 + h * 16;
        float qv[16];
        #pragma unroll
        for (int d = 0; d < 16; d++) qv[d] = __ldg(qp + d);
        float s[8];
        #pragma unroll
        for (int j = 0; j < 8; j++) {
            int key = lane + 32 * j;
            float a = 0.f;
            #pragma unroll
            for (int d = 0; d < 16; d++) a += qv[d] * Ks[key][d];
            s[j] = a * 0.25f;
        }
        float mx = s[0];
        #pragma unroll
        for (int j = 1; j < 8; j++) mx = fmaxf(mx, s[j]);
        #pragma unroll
        for (int o = 16; o > 0; o >>= 1) mx = fmaxf(mx, __shfl_xor_sync(0xffffffffu, mx, o));
        float sm = 0.f;
        #pragma unroll
        for (int j = 0; j < 8; j++) { s[j] = __expf(s[j] - mx); sm += s[j]; }
        #pragma unroll
        for (int o = 16; o > 0; o >>= 1) sm += __shfl_xor_sync(0xffffffffu, sm, o);
        float inv = __fdividef(1.0f, sm);
        float acc[16];
        #pragma unroll
        for (int d = 0; d < 16; d++) acc[d] = 0.f;
        #pragma unroll
        for (int j = 0; j < 8; j++) {
            int key = lane + 32 * j;
            float p = s[j];
            #pragma unroll
            for (int d = 0; d < 16; d++) acc[d] += p * Vs[key][d];
        }
        #pragma unroll
        for (int d = 0; d < 16; d++) {
            #pragma unroll
            for (int o = 16; o > 0; o >>= 1) acc[d] += __shfl_xor_sync(0xffffffffu, acc[d], o);
            acc[d] *= inv;
        }
        if (lane == 0) {
            float* op = oh + ((size_t)b * 1024 + q) * 128 + h * 16;
            #pragma unroll
            for (int d = 0; d < 16; d++) op[d] = cvtf(acc[d]);
        }
    }
}

// ---------------- mean partials ----------------
__global__ void __launch_bounds__(128) k_fpart(const float* __restrict__ hatt,
        float* __restrict__ part) {
    int b = blockIdx.x, ch = blockIdx.y, t = threadIdx.x;
    const float* p = hatt + (size_t)b * 131072 + (size_t)ch * 128 * 128 + t;
    float s = 0.f;
    #pragma unroll 8
    for (int n = 0; n < 128; n++) s += p[(size_t)n * 128];
    part[(b * 8 + ch) * 128 + t] = s;
}

// ---------------- state_value + mask + stage ----------------
__global__ void k_final2(const float* __restrict__ hnum, const float* __restrict__ part,
                         const float* __restrict__ stage, float* __restrict__ out) {
    int b = blockIdx.x, t = threadIdx.x;
    float* sv = out + 4194304 + (size_t)b * 258;
    if (t < 128) {
        sv[t] = hnum[b * 128 + t];
        float s = 0.f;
        #pragma unroll
        for (int c = 0; c < 8; c++) s += part[(b * 8 + c) * 128 + t];
        sv[128 + t] = s * (1.0f / 1024.0f);
    }
    if (t < 2) {
        sv[256 + t] = stage[b * 2 + t];
        out[4235328 + b * 2 + t] = stage[b * 2 + t];
    }
    for (int i = t; i < 1024; i += 256) out[4202560 + b * 1024 + i] = 1.0f;
}

extern "C" void kernel_launch(void* const* d_in, const int* in_sizes, int n_in,
                              void* d_out, int out_size) {
    const float* numerical = (const float*)d_in[0];
    const float* node_feature = (const float*)d_in[1];
    const float* stage = (const float*)d_in[2];
    const float* W_num0 = (const float*)d_in[3];
    const float* b_num0 = (const float*)d_in[4];
    const float* W_num1 = (const float*)d_in[5];
    const float* b_num1 = (const float*)d_in[6];
    const float* W_node = (const float*)d_in[7];
    const float* b_node = (const float*)d_in[8];
    const float* pos_enc = (const float*)d_in[9];
    const float* ew1 = (const float*)d_in[10];
    const float* eb1 = (const float*)d_in[11];
    const float* ew2 = (const float*)d_in[12];
    const float* eb2 = (const float*)d_in[13];
    const float* Wg = (const float*)d_in[14];
    const float* bg = (const float*)d_in[15];
    const float* Wu = (const float*)d_in[16];
    const float* bu = (const float*)d_in[17];
    const float* Wq1 = (const float*)d_in[18];
    const float* bq1 = (const float*)d_in[19];
    const float* Wk1 = (const float*)d_in[20];
    const float* bk1 = (const float*)d_in[21];
    const float* Wv1 = (const float*)d_in[22];
    const float* bv1 = (const float*)d_in[23];
    const float* W_in = (const float*)d_in[24];
    const float* b_in = (const float*)d_in[25];
    const float* W_out = (const float*)d_in[26];
    const float* b_out = (const float*)d_in[27];
    const int* e_dis = (const int*)d_in[28];
    const int* e_od = (const int*)d_in[29];
    const int* build_idx = (const int*)d_in[31];
    float* out = (float*)d_out;

    float* S = nullptr;
    cudaGetSymbolAddress((void**)&S, g_scratch);
    float* H    = S + OFF_H;
    float* T0a  = S + OFF_T0A;
    float* T0b  = S + OFF_T0B;
    float* Ma   = S + OFF_MA;
    float* Mb   = S + OFF_MB;
    float* AVGa = S + OFF_AVGA;
    float* AVGb = S + OFF_AVGB;
    int* ADJa   = (int*)(S + OFF_ADJA);
    int* ADJb   = (int*)(S + OFF_ADJB);
    int* CNTIa  = (int*)(S + OFF_CNTIA);
    int* CNTIb  = (int*)(S + OFF_CNTIB);
    float* GTa  = S + OFF_GTA;
    float* UTa  = S + OFF_UTA;
    float* GTb  = S + OFF_GTB;
    float* UTb  = S + OFF_UTB;
    float* HC   = S + OFF_HC;
    float* Q2   = S + OFF_Q2;
    float* K2   = S + OFF_K2;
    float* V2   = S + OFF_V2;
    float* OH   = S + OFF_OH;
    float* HNUM = S + OFF_HNUM;
    float* PART = S + OFF_PART;

    cudaFuncSetAttribute(gemm_tc, cudaFuncAttributeMaxDynamicSharedMemorySize,
                         GEMM_SMEM_BYTES);

    const int BIG = 1 << 30;

    // zero adjacency counters (256 KB)
    cudaMemsetAsync(CNTIa, 0, 2 * 32768 * sizeof(int));

    // pre-round weights to canonical tf32
    {
        RJobs rj = {};
        rj.src[0] = ew1 + 2 * 16384; rj.dst[0] = S + OFF_RE1A; rj.n[0] = 16384;
        rj.src[1] = ew1 + 3 * 16384; rj.dst[1] = S + OFF_RE1B; rj.n[1] = 16384;
        rj.src[2] = ew2 + 2 * 16384; rj.dst[2] = S + OFF_RE2A; rj.n[2] = 16384;
        rj.src[3] = ew2 + 3 * 16384; rj.dst[3] = S + OFF_RE2B; rj.n[3] = 16384;
        rj.src[4] = Wg;              rj.dst[4] = S + OFF_RWG;  rj.n[4] = 32768;
        rj.src[5] = Wu;              rj.dst[5] = S + OFF_RWU;  rj.n[5] = 32768;
        rj.src[6] = W_out;           rj.dst[6] = S + OFF_RWOUT; rj.n[6] = 16384;
        k_roundW<<<dim3(128, 7), 256>>>(rj);
    }

    k_build<<<4096, 256>>>(e_dis, e_od, ADJa, CNTIa, ADJb, CNTIb);
    k_hnum<<<32, 256>>>(numerical, W_num0, b_num0, W_num1, b_num1, HNUM);
    k_embed<<<4096, 128>>>(node_feature, W_node, b_node, pos_enc, H);
    k_fuseW2<<<dim3(3, 9), 128>>>(Wq1, bq1, Wk1, bk1, Wv1, bv1, W_in, b_in, S);

    // edge-MLP layer 1 (only surviving L_GCN iteration), both passes batched
    {
        Jobs j = {};
        j.X[0] = H;   j.W[0] = S + OFF_RE1A; j.B[0] = eb1 + 2 * 128; j.Y[0] = T0a;
        j.X[1] = H;   j.W[1] = S + OFF_RE2A; j.B[1] = eb2 + 2 * 128; j.Y[1] = T0b;
        gemm_tc<<<dim3(256, 2), 256, GEMM_SMEM_BYTES>>>(j, 128, BIG, 0, nullptr, 128, 128, 3);
    }
    {
        Jobs j = {};
        j.X[0] = T0a; j.W[0] = S + OFF_RE1B; j.B[0] = eb1 + 3 * 128; j.Y[0] = Ma;
        j.X[1] = T0b; j.W[1] = S + OFF_RE2B; j.B[1] = eb2 + 3 * 128; j.Y[1] = Mb;
        gemm_tc<<<dim3(256, 2), 256, GEMM_SMEM_BYTES>>>(j, 128, BIG, 0, nullptr, 128, 128, 1);
    }

    // gather: AVG = cvtf(sum(m[nbr]) / (cnt + eps))
    k_gather<<<8192, 256>>>(ADJa, CNTIa, ADJb, CNTIb, Ma, Mb, AVGa, AVGb);

    // gate/update GEMMs, comb fused (K=256: k<128 from H, k>=128 from AVG)
    {
        Jobs j = {};
        j.X[0] = H; j.W[0] = S + OFF_RWG; j.B[0] = bg; j.Y[0] = GTa; j.SUM[0] = AVGa;
        j.X[1] = H; j.W[1] = S + OFF_RWU; j.B[1] = bu; j.Y[1] = UTa; j.SUM[1] = AVGa;
        j.X[2] = H; j.W[2] = S + OFF_RWG; j.B[2] = bg; j.Y[2] = GTb; j.SUM[2] = AVGb;
        j.X[3] = H; j.W[3] = S + OFF_RWU; j.B[3] = bu; j.Y[3] = UTb; j.SUM[3] = AVGb;
        gemm_tc<<<dim3(256, 4), 256, GEMM_SMEM_BYTES>>>(j, 128, BIG, 0, nullptr, 128, 256, 1);
    }
    k_gcomb<<<8192, 256>>>(GTa, UTa, GTb, UTb, H, HC);

    {
        Jobs j = {};
        j.X[0] = HC; j.W[0] = S + OFF_WQF; j.B[0] = S + OFF_BQF; j.Y[0] = Q2;
        gemm_tc<<<dim3(256, 1), 256, GEMM_SMEM_BYTES>>>(j, 256, BIG, 0, nullptr, 128, 256, 0);
    }
    {
        Jobs j = {};
        j.X[0] = HC; j.W[0] = S + OFF_WKF; j.B[0] = S + OFF_BKF; j.Y[0] = K2;
        j.X[1] = HC; j.W[1] = S + OFF_WVF; j.B[1] = S + OFF_BVF; j.Y[1] = V2;
        gemm_tc<<<dim3(64, 2), 256, GEMM_SMEM_BYTES>>>(j, 256, 256, 262144, build_idx, 128, 256, 0);
    }
    k_attn<<<dim3(8, 32), 512>>>(Q2, K2, V2, OH);
    {
        Jobs j = {};
        j.X[0] = OH; j.W[0] = S + OFF_RWOUT; j.B[0] = b_out; j.Y[0] = out;
        gemm_tc<<<dim3(256, 1), 256, GEMM_SMEM_BYTES>>>(j, 128, BIG, 0, nullptr, 128, 128, 0);
    }
    k_fpart<<<dim3(32, 8), 128>>>(out, PART);
    k_final2<<<32, 256>>>(HNUM, PART, stage, out);
}

// round 9
// speedup vs baseline: 3.7631x; 1.3700x over previous
#include <cuda_runtime.h>
#include <math.h>
#include <stdint.h>

#define NNODE 1024
#define EPS_F 1e-6f

// ---- scratch layout (floats) ----
#define OFF_H     ((size_t)0)
#define OFF_T0A   (OFF_H    + 4194304)
#define OFF_T0B   (OFF_T0A  + 4194304)
#define OFF_MA    (OFF_T0B  + 4194304)
#define OFF_MB    (OFF_MA   + 4194304)
#define OFF_AVGA  (OFF_MB   + 4194304)
#define OFF_AVGB  (OFF_AVGA + 4194304)
#define OFF_ADJA  (OFF_AVGB + 4194304)
#define OFF_ADJB  (OFF_ADJA + 4194304)
#define OFF_CNTIA (OFF_ADJB + 4194304)
#define OFF_CNTIB (OFF_CNTIA + 32768)
#define OFF_GTA   (OFF_CNTIB + 32768)
#define OFF_UTA   (OFF_GTA  + 4194304)
#define OFF_GTB   (OFF_UTA  + 4194304)
#define OFF_UTB   (OFF_GTB  + 4194304)
#define OFF_HC    (OFF_UTB  + 4194304)
#define OFF_Q2    (OFF_HC   + 8388608)
#define OFF_K2    (OFF_Q2   + 4194304)
#define OFF_V2    (OFF_K2   + 1048576)
#define OFF_OH    (OFF_V2   + 1048576)
#define OFF_HNUM  (OFF_OH   + 4194304)
#define OFF_WQF   (OFF_HNUM + 4096)
#define OFF_BQF   (OFF_WQF  + 32768)
#define OFF_WKF   (OFF_BQF  + 128)
#define OFF_BKF   (OFF_WKF  + 32768)
#define OFF_WVF   (OFF_BKF  + 128)
#define OFF_BVF   (OFF_WVF  + 32768)
#define OFF_PART  (OFF_BVF  + 128)
#define OFF_RE1A  (OFF_PART + 32768)
#define OFF_RE1B  (OFF_RE1A + 16384)
#define OFF_RE2A  (OFF_RE1B + 16384)
#define OFF_RE2B  (OFF_RE2A + 16384)
#define OFF_RWG   (OFF_RE2B + 16384)
#define OFF_RWU   (OFF_RWG  + 32768)
#define OFF_RWOUT (OFF_RWU  + 32768)
#define OFF_RNF   (OFF_RWOUT + 16384)
#define OFF_RWN   (OFF_RNF  + 1048576)
#define SCRATCH_FLOATS (OFF_RWN + 4096)

__device__ float g_scratch[SCRATCH_FLOATS];

__device__ __forceinline__ float ftanh(float x) {
    float t = __expf(2.0f * x);
    return 1.0f - __fdividef(2.0f, t + 1.0f);
}

__device__ __forceinline__ unsigned cvtu(float x) {
    unsigned u;
    asm("cvt.rna.tf32.f32 %0, %1;" : "=r"(u) : "f"(x));
    return u;
}

__device__ __forceinline__ float cvtf(float x) {
    return __uint_as_float(cvtu(x));
}

__device__ __forceinline__ void mma8(float4& c, const unsigned* a, unsigned b0, unsigned b1) {
    asm volatile("mma.sync.aligned.m16n8k8.row.col.f32.tf32.tf32.f32 "
        "{%0,%1,%2,%3}, {%4,%5,%6,%7}, {%8,%9}, {%0,%1,%2,%3};"
        : "+f"(c.x), "+f"(c.y), "+f"(c.z), "+f"(c.w)
        : "r"(a[0]), "r"(a[1]), "r"(a[2]), "r"(a[3]), "r"(b0), "r"(b1));
}

__device__ __forceinline__ void cpa16(void* s, const void* g) {
    unsigned sa = (unsigned)__cvta_generic_to_shared(s);
    asm volatile("cp.async.cg.shared.global [%0], [%1], 16;" :: "r"(sa), "l"(g));
}

// ---------------- pre-rounding (to canonical tf32) ----------------
struct RJobs {
    const float* src[9];
    float* dst[9];
    int n[9];
};
__global__ void k_roundW(RJobs j) {
    int job = blockIdx.y;
    int i = blockIdx.x * 256 + threadIdx.x;
    if (i < j.n[job]) j.dst[job][i] = cvtf(j.src[job][i]);
}

// ---------------- h_num ----------------
__global__ void k_hnum(const float* __restrict__ num, const float* __restrict__ W0,
                       const float* __restrict__ b0, const float* __restrict__ W1,
                       const float* __restrict__ b1, float* __restrict__ out) {
    __shared__ float xs[64];
    __shared__ float hid[256];
    int b = blockIdx.x, t = threadIdx.x;
    if (t < 64) xs[t] = num[b * 64 + t];
    __syncthreads();
    float a = b0[t];
    #pragma unroll 8
    for (int k = 0; k < 64; k++) a += xs[k] * W0[k * 256 + t];
    hid[t] = ftanh(a);
    __syncthreads();
    if (t < 128) {
        float a2 = b1[t];
        #pragma unroll 8
        for (int k = 0; k < 256; k++) a2 += hid[k] * W1[k * 128 + t];
        out[b * 128 + t] = ftanh(a2);
    }
}

// ---------------- batched tf32 GEMM: 128x128 tile, cp.async double buffer ----------------
// act bit0 = tanh, bit1 = round output to tf32
// comb mode (SUM != null): K=256, k<128 reads X, k>=128 reads SUM
// pos mode (POS != null): out = cvtf(tanh(out) + POS[(row&1023)*128+col])
struct Jobs {
    const float* X[4];
    const float* W[4];
    const float* B[4];
    float* Y[4];
    const float* SUM[4];
    const float* POS[4];
};

#define XPITCH 36
#define WPITCH 132
#define SM_XB (2 * 128 * XPITCH)
#define SM_WB (2 * 32 * WPITCH)
#define GEMM_SMEM_BYTES ((SM_XB + SM_WB + 128) * 4)

__global__ void __launch_bounds__(256, 2) gemm_tc(Jobs jobs, int ldx, int rpb,
        size_t bstride, const int* __restrict__ rowmap, int ldy, int K, int act) {
    extern __shared__ float sm[];
    float* Xs = sm;
    float* Ws = sm + SM_XB;
    unsigned* rowoff = (unsigned*)(sm + SM_XB + SM_WB);

    const float* __restrict__ X = jobs.X[blockIdx.y];
    const float* __restrict__ W = jobs.W[blockIdx.y];
    const float* __restrict__ bias = jobs.B[blockIdx.y];
    float* __restrict__ Y = jobs.Y[blockIdx.y];
    const float* __restrict__ SUM = jobs.SUM[blockIdx.y];
    const float* __restrict__ PS = jobs.POS[blockIdx.y];
    bool mode = (SUM != nullptr);

    int tid = threadIdx.x;
    int rbase = blockIdx.x * 128;
    if (tid < 128) {
        int r = rbase + tid;
        int bb = r / rpb;
        int n = r - bb * rpb;
        if (rowmap) n = rowmap[n];
        rowoff[tid] = (unsigned)((size_t)bb * bstride + (size_t)n * ldx);
    }
    __syncthreads();

    int wid = tid >> 5, lane = tid & 31;
    int wm = (wid & 3) * 32;
    int wn = (wid >> 2) * 64;
    int gid = lane >> 2, tig = lane & 3;

    float4 c[2][8];
    #pragma unroll
    for (int i = 0; i < 2; i++)
        #pragma unroll
        for (int j = 0; j < 8; j++) c[i][j] = make_float4(0.f, 0.f, 0.f, 0.f);

    int nk = K >> 5;
    if (K == 32) nk = 1;

    #define STAGE(IB) do { \
        int kb_ = (IB) * 32; \
        int buf_ = (IB) & 1; \
        const float* xb_ = X; int ko_ = kb_; \
        if (mode && kb_ >= 128) { xb_ = SUM; ko_ = kb_ - 128; } \
        _Pragma("unroll") \
        for (int p_ = 0; p_ < 4; p_++) { \
            int id_ = p_ * 256 + tid; \
            int r_ = id_ >> 3, c_ = (id_ & 7) * 4; \
            cpa16(&Xs[buf_ * 128 * XPITCH + r_ * XPITCH + c_], xb_ + rowoff[r_] + ko_ + c_); \
        } \
        _Pragma("unroll") \
        for (int p_ = 0; p_ < 4; p_++) { \
            int id_ = p_ * 256 + tid; \
            int k_ = id_ >> 5, c_ = (id_ & 31) * 4; \
            cpa16(&Ws[buf_ * 32 * WPITCH + k_ * WPITCH + c_], W + (size_t)(kb_ + k_) * 128 + c_); \
        } \
    } while (0)

    STAGE(0);
    asm volatile("cp.async.commit_group;");

    for (int ib = 0; ib < nk; ib++) {
        if (ib + 1 < nk) {
            STAGE(ib + 1);
            asm volatile("cp.async.commit_group;");
            asm volatile("cp.async.wait_group 1;");
        } else {
            asm volatile("cp.async.wait_group 0;");
        }
        __syncthreads();
        float* Xb = Xs + (ib & 1) * 128 * XPITCH;
        float* Wb = Ws + (ib & 1) * 32 * WPITCH;
        int kmax = (K == 32) ? 4 : 4;
        #pragma unroll
        for (int ks = 0; ks < 4; ks++) {
            if (ks >= kmax) break;
            int kk = ks * 8;
            unsigned a[2][4];
            #pragma unroll
            for (int mt = 0; mt < 2; mt++) {
                int m = wm + mt * 16 + gid;
                a[mt][0] = __float_as_uint(Xb[m * XPITCH + kk + tig]);
                a[mt][1] = __float_as_uint(Xb[(m + 8) * XPITCH + kk + tig]);
                a[mt][2] = __float_as_uint(Xb[m * XPITCH + kk + tig + 4]);
                a[mt][3] = __float_as_uint(Xb[(m + 8) * XPITCH + kk + tig + 4]);
            }
            #pragma unroll
            for (int nt = 0; nt < 8; nt++) {
                int n = wn + nt * 8 + gid;
                unsigned b0 = __float_as_uint(Wb[(kk + tig) * WPITCH + n]);
                unsigned b1 = __float_as_uint(Wb[(kk + tig + 4) * WPITCH + n]);
                mma8(c[0][nt], a[0], b0, b1);
                mma8(c[1][nt], a[1], b0, b1);
            }
        }
        __syncthreads();
    }

    #pragma unroll
    for (int nt = 0; nt < 8; nt++) {
        int col = wn + nt * 8 + tig * 2;
        float bz0 = bias[col], bz1 = bias[col + 1];
        #pragma unroll
        for (int mt = 0; mt < 2; mt++) {
            int row0 = rbase + wm + mt * 16 + gid;
            float4 cc = c[mt][nt];
            float o00 = cc.x + bz0, o01 = cc.y + bz1;
            float o10 = cc.z + bz0, o11 = cc.w + bz1;
            if (PS) {
                int p0 = (row0 & 1023) * 128 + col;
                int p1 = ((row0 + 8) & 1023) * 128 + col;
                o00 = cvtf(ftanh(o00) + PS[p0]);
                o01 = cvtf(ftanh(o01) + PS[p0 + 1]);
                o10 = cvtf(ftanh(o10) + PS[p1]);
                o11 = cvtf(ftanh(o11) + PS[p1 + 1]);
            } else {
                if (act & 1) { o00 = ftanh(o00); o01 = ftanh(o01); o10 = ftanh(o10); o11 = ftanh(o11); }
                if (act & 2) { o00 = cvtf(o00); o01 = cvtf(o01); o10 = cvtf(o10); o11 = cvtf(o11); }
            }
            *(float2*)(Y + (size_t)row0 * ldy + col) = make_float2(o00, o01);
            *(float2*)(Y + (size_t)(row0 + 8) * ldy + col) = make_float2(o10, o11);
        }
    }
}

// ---------------- adjacency build: one thread per edge ----------------
__global__ void __launch_bounds__(256) k_build(const int* __restrict__ e0,
        const int* __restrict__ e1, int* __restrict__ adjA, int* __restrict__ cntA,
        int* __restrict__ adjB, int* __restrict__ cntB) {
    int i = blockIdx.x * 256 + threadIdx.x;
    int pass = i >= 524288;
    int e = pass ? i - 524288 : i;
    const int* eidx = pass ? e1 : e0;
    int* adj = pass ? adjB : adjA;
    int* cnt = pass ? cntB : cntA;
    int b = e >> 14;
    int2 ab = __ldg((const int2*)eidx + e);
    int na = b * NNODE + ab.x;
    int nb = b * NNODE + ab.y;
    int p = atomicAdd(&cnt[na], 1);
    if (p < 128) adj[na * 128 + p] = nb;
    int q = atomicAdd(&cnt[nb], 1);
    if (q < 128) adj[nb * 128 + q] = na;
}

// ---------------- gather: one warp per (node, pass); AVG = cvtf(sum * rcp) ----------------
__global__ void __launch_bounds__(256) k_gather(const int* __restrict__ adjA,
        const int* __restrict__ cntA, const int* __restrict__ adjB,
        const int* __restrict__ cntB, const float* __restrict__ Ma,
        const float* __restrict__ Mb, float* __restrict__ AVGa, float* __restrict__ AVGb) {
    int gw = (blockIdx.x * 256 + threadIdx.x) >> 5;
    int lane = threadIdx.x & 31;
    int pass = gw >= 32768;
    int row = gw & 32767;
    const int* adj = (pass ? adjB : adjA) + row * 128;
    int cnt = (pass ? cntB : cntA)[row];
    const float* m = pass ? Mb : Ma;
    float* avg = pass ? AVGb : AVGa;
    int n = min(cnt, 128);
    float4 acc = make_float4(0.f, 0.f, 0.f, 0.f);
    int i = 0;
    for (; i + 4 <= n; i += 4) {
        int4 nb = *(const int4*)(adj + i);
        float4 v0 = __ldg((const float4*)(m + (size_t)nb.x * 128) + lane);
        float4 v1 = __ldg((const float4*)(m + (size_t)nb.y * 128) + lane);
        float4 v2 = __ldg((const float4*)(m + (size_t)nb.z * 128) + lane);
        float4 v3 = __ldg((const float4*)(m + (size_t)nb.w * 128) + lane);
        acc.x += v0.x + v1.x + v2.x + v3.x;
        acc.y += v0.y + v1.y + v2.y + v3.y;
        acc.z += v0.z + v1.z + v2.z + v3.z;
        acc.w += v0.w + v1.w + v2.w + v3.w;
    }
    for (; i < n; i++) {
        int nb = adj[i];
        float4 v = __ldg((const float4*)(m + (size_t)nb * 128) + lane);
        acc.x += v.x; acc.y += v.y; acc.z += v.z; acc.w += v.w;
    }
    float rcp = __fdividef(1.0f, (float)cnt + EPS_F);
    float4 o;
    o.x = cvtf(acc.x * rcp); o.y = cvtf(acc.y * rcp);
    o.z = cvtf(acc.z * rcp); o.w = cvtf(acc.w * rcp);
    *(float4*)(avg + (size_t)row * 128 + lane * 4) = o;
}

// ---------------- gate combine (output rounded for Q/K/V GEMMs) ----------------
__global__ void __launch_bounds__(256) k_gcomb(const float* __restrict__ GTa,
        const float* __restrict__ UTa, const float* __restrict__ GTb,
        const float* __restrict__ UTb, const float* __restrict__ h,
        float* __restrict__ hc) {
    int i = blockIdx.x * 256 + threadIdx.x;
    int pass = i >= 1048576;
    int j = pass ? i - 1048576 : i;
    int row = j >> 5, q = j & 31;
    const float* GT = pass ? GTb : GTa;
    const float* UT = pass ? UTb : UTa;
    float4 g = __ldg((const float4*)(GT + (size_t)row * 128) + q);
    float4 u = __ldg((const float4*)(UT + (size_t)row * 128) + q);
    float4 hv = __ldg((const float4*)(h + (size_t)row * 128) + q);
    float4 o;
    o.x = cvtf(g.x * u.x + (1.0f - g.x) * hv.x);
    o.y = cvtf(g.y * u.y + (1.0f - g.y) * hv.y);
    o.z = cvtf(g.z * u.z + (1.0f - g.z) * hv.z);
    o.w = cvtf(g.w * u.w + (1.0f - g.w) * hv.w);
    *(float4*)(hc + (size_t)row * 256 + pass * 128 + q * 4) = o;
}

// ---------------- fold W_in into Wq1/Wk1/Wv1 (tiled, coalesced) ----------------
__global__ void __launch_bounds__(128) k_fuseW2(const float* __restrict__ Wq1,
        const float* __restrict__ bq1, const float* __restrict__ Wk1,
        const float* __restrict__ bk1, const float* __restrict__ Wv1,
        const float* __restrict__ bv1, const float* __restrict__ W_in,
        const float* __restrict__ b_in, float* __restrict__ S) {
    int mat = blockIdx.x;
    int rb = blockIdx.y;
    int c = threadIdx.x;
    const float* Wsrc = mat == 0 ? Wq1 : (mat == 1 ? Wk1 : Wv1);
    const float* bsrc = mat == 0 ? bq1 : (mat == 1 ? bk1 : bv1);
    float* Wd = S + (mat == 0 ? OFF_WQF : (mat == 1 ? OFF_WKF : OFF_WVF));
    float* bd = S + (mat == 0 ? OFF_BQF : (mat == 1 ? OFF_BKF : OFF_BVF));
    if (rb == 8) {
        __shared__ float bs[128];
        bs[c] = bsrc[c];
        __syncthreads();
        float a = 0.f;
        #pragma unroll 8
        for (int k = 0; k < 128; k++) a += bs[k] * W_in[k * 384 + mat * 128 + c];
        bd[c] = a + b_in[mat * 128 + c];
        return;
    }
    __shared__ float Win[16][128];
    __shared__ float Xs[32][17];
    int r0 = rb * 32;
    float acc[32];
    #pragma unroll
    for (int r = 0; r < 32; r++) acc[r] = 0.f;
    for (int kb = 0; kb < 128; kb += 16) {
        __syncthreads();
        #pragma unroll
        for (int k = 0; k < 16; k++) Win[k][c] = W_in[(kb + k) * 384 + mat * 128 + c];
        #pragma unroll
        for (int p = 0; p < 4; p++) {
            int idx = p * 128 + c;
            int r = idx >> 4, k = idx & 15;
            Xs[r][k] = Wsrc[(r0 + r) * 128 + kb + k];
        }
        __syncthreads();
        #pragma unroll
        for (int k = 0; k < 16; k++) {
            float w = Win[k][c];
            #pragma unroll
            for (int r = 0; r < 32; r++) acc[r] += Xs[r][k] * w;
        }
    }
    #pragma unroll
    for (int r = 0; r < 32; r++) Wd[(r0 + r) * 128 + c] = cvtf(acc[r]);
}

// ---------------- attention: 2 queries/warp, reduce-scatter output ----------------
__global__ void __launch_bounds__(256) k_attn(const float* __restrict__ q2,
        const float* __restrict__ k2, const float* __restrict__ v2,
        float* __restrict__ oh) {
    int h = blockIdx.x, b = blockIdx.y;
    __shared__ float Ks[256][17];
    __shared__ float Vs[256][17];
    int tid = threadIdx.x;
    for (int i = tid; i < 4096; i += 256) {
        int k = i >> 4, d = i & 15;
        Ks[k][d] = k2[((size_t)b * 256 + k) * 128 + h * 16 + d];
        Vs[k][d] = v2[((size_t)b * 256 + k) * 128 + h * 16 + d];
    }
    __syncthreads();
    int warp = tid >> 5, lane = tid & 31;
    int dmap = ((lane >> 4) & 1) * 8 + ((lane >> 3) & 1) * 4 +
               ((lane >> 2) & 1) * 2 + ((lane >> 1) & 1);
    for (int q0 = warp * 2; q0 < 1024; q0 += 16) {
        float qv[2][16];
        #pragma unroll
        for (int qq = 0; qq < 2; qq++) {
            const float* qp = q2 + ((size_t)b * 1024 + q0 + qq) * 128 + h * 16;
            #pragma unroll
            for (int p = 0; p < 4; p++) {
                float4 v = __ldg((const float4*)qp + p);
                qv[qq][p * 4] = v.x; qv[qq][p * 4 + 1] = v.y;
                qv[qq][p * 4 + 2] = v.z; qv[qq][p * 4 + 3] = v.w;
            }
        }
        float s[2][8];
        #pragma unroll
        for (int j = 0; j < 8; j++) {
            int key = lane + 32 * j;
            float a0 = 0.f, a1 = 0.f;
            #pragma unroll
            for (int d = 0; d < 16; d++) {
                float kv = Ks[key][d];
                a0 += qv[0][d] * kv;
                a1 += qv[1][d] * kv;
            }
            s[0][j] = a0 * 0.25f;
            s[1][j] = a1 * 0.25f;
        }
        float inv[2];
        #pragma unroll
        for (int qq = 0; qq < 2; qq++) {
            float mx = s[qq][0];
            #pragma unroll
            for (int j = 1; j < 8; j++) mx = fmaxf(mx, s[qq][j]);
            #pragma unroll
            for (int o = 16; o > 0; o >>= 1) mx = fmaxf(mx, __shfl_xor_sync(0xffffffffu, mx, o));
            float sm = 0.f;
            #pragma unroll
            for (int j = 0; j < 8; j++) { s[qq][j] = __expf(s[qq][j] - mx); sm += s[qq][j]; }
            #pragma unroll
            for (int o = 16; o > 0; o >>= 1) sm += __shfl_xor_sync(0xffffffffu, sm, o);
            inv[qq] = __fdividef(1.0f, sm);
        }
        float acc[2][16];
        #pragma unroll
        for (int qq = 0; qq < 2; qq++)
            #pragma unroll
            for (int d = 0; d < 16; d++) acc[qq][d] = 0.f;
        #pragma unroll
        for (int j = 0; j < 8; j++) {
            int key = lane + 32 * j;
            float p0 = s[0][j], p1 = s[1][j];
            #pragma unroll
            for (int d = 0; d < 16; d++) {
                float vv = Vs[key][d];
                acc[0][d] += p0 * vv;
                acc[1][d] += p1 * vv;
            }
        }
        #pragma unroll
        for (int qq = 0; qq < 2; qq++) {
            float* v = acc[qq];
            #pragma unroll
            for (int r = 0; r < 4; r++) {
                int m = 16 >> r;
                int L = 8 >> r;
                #pragma unroll
                for (int i = 0; i < 8; i++) {
                    if (i >= L) break;
                    float sel = (lane & m) ? v[i] : v[i + L];
                    float rr = __shfl_xor_sync(0xffffffffu, sel, m);
                    v[i] = ((lane & m) ? v[i + L] : v[i]) + rr;
                }
            }
            v[0] += __shfl_xor_sync(0xffffffffu, v[0], 1);
            if (!(lane & 1)) {
                oh[((size_t)b * 1024 + q0 + qq) * 128 + h * 16 + dmap] = cvtf(v[0] * inv[qq]);
            }
        }
    }
}

// ---------------- mean partials ----------------
__global__ void __launch_bounds__(128) k_fpart(const float* __restrict__ hatt,
        float* __restrict__ part) {
    int b = blockIdx.x, ch = blockIdx.y, t = threadIdx.x;
    const float* p = hatt + (size_t)b * 131072 + (size_t)ch * 128 * 128 + t;
    float s = 0.f;
    #pragma unroll 8
    for (int n = 0; n < 128; n++) s += p[(size_t)n * 128];
    part[(b * 8 + ch) * 128 + t] = s;
}

// ---------------- state_value + mask + stage ----------------
__global__ void k_final2(const float* __restrict__ hnum, const float* __restrict__ part,
                         const float* __restrict__ stage, float* __restrict__ out) {
    int b = blockIdx.x, t = threadIdx.x;
    float* sv = out + 4194304 + (size_t)b * 258;
    if (t < 128) {
        sv[t] = hnum[b * 128 + t];
        float s = 0.f;
        #pragma unroll
        for (int c = 0; c < 8; c++) s += part[(b * 8 + c) * 128 + t];
        sv[128 + t] = s * (1.0f / 1024.0f);
    }
    if (t < 2) {
        sv[256 + t] = stage[b * 2 + t];
        out[4235328 + b * 2 + t] = stage[b * 2 + t];
    }
    for (int i = t; i < 1024; i += 256) out[4202560 + b * 1024 + i] = 1.0f;
}

extern "C" void kernel_launch(void* const* d_in, const int* in_sizes, int n_in,
                              void* d_out, int out_size) {
    const float* numerical = (const float*)d_in[0];
    const float* node_feature = (const float*)d_in[1];
    const float* stage = (const float*)d_in[2];
    const float* W_num0 = (const float*)d_in[3];
    const float* b_num0 = (const float*)d_in[4];
    const float* W_num1 = (const float*)d_in[5];
    const float* b_num1 = (const float*)d_in[6];
    const float* W_node = (const float*)d_in[7];
    const float* b_node = (const float*)d_in[8];
    const float* pos_enc = (const float*)d_in[9];
    const float* ew1 = (const float*)d_in[10];
    const float* eb1 = (const float*)d_in[11];
    const float* ew2 = (const float*)d_in[12];
    const float* eb2 = (const float*)d_in[13];
    const float* Wg = (const float*)d_in[14];
    const float* bg = (const float*)d_in[15];
    const float* Wu = (const float*)d_in[16];
    const float* bu = (const float*)d_in[17];
    const float* Wq1 = (const float*)d_in[18];
    const float* bq1 = (const float*)d_in[19];
    const float* Wk1 = (const float*)d_in[20];
    const float* bk1 = (const float*)d_in[21];
    const float* Wv1 = (const float*)d_in[22];
    const float* bv1 = (const float*)d_in[23];
    const float* W_in = (const float*)d_in[24];
    const float* b_in = (const float*)d_in[25];
    const float* W_out = (const float*)d_in[26];
    const float* b_out = (const float*)d_in[27];
    const int* e_dis = (const int*)d_in[28];
    const int* e_od = (const int*)d_in[29];
    const int* build_idx = (const int*)d_in[31];
    float* out = (float*)d_out;

    float* S = nullptr;
    cudaGetSymbolAddress((void**)&S, g_scratch);
    float* H    = S + OFF_H;
    float* T0a  = S + OFF_T0A;
    float* T0b  = S + OFF_T0B;
    float* Ma   = S + OFF_MA;
    float* Mb   = S + OFF_MB;
    float* AVGa = S + OFF_AVGA;
    float* AVGb = S + OFF_AVGB;
    int* ADJa   = (int*)(S + OFF_ADJA);
    int* ADJb   = (int*)(S + OFF_ADJB);
    int* CNTIa  = (int*)(S + OFF_CNTIA);
    int* CNTIb  = (int*)(S + OFF_CNTIB);
    float* GTa  = S + OFF_GTA;
    float* UTa  = S + OFF_UTA;
    float* GTb  = S + OFF_GTB;
    float* UTb  = S + OFF_UTB;
    float* HC   = S + OFF_HC;
    float* Q2   = S + OFF_Q2;
    float* K2   = S + OFF_K2;
    float* V2   = S + OFF_V2;
    float* OH   = S + OFF_OH;
    float* HNUM = S + OFF_HNUM;
    float* PART = S + OFF_PART;

    cudaFuncSetAttribute(gemm_tc, cudaFuncAttributeMaxDynamicSharedMemorySize,
                         GEMM_SMEM_BYTES);

    const int BIG = 1 << 30;

    cudaMemsetAsync(CNTIa, 0, 2 * 32768 * sizeof(int));

    // pre-round weights + node_feature to canonical tf32
    {
        RJobs rj = {};
        rj.src[0] = ew1 + 2 * 16384; rj.dst[0] = S + OFF_RE1A; rj.n[0] = 16384;
        rj.src[1] = ew1 + 3 * 16384; rj.dst[1] = S + OFF_RE1B; rj.n[1] = 16384;
        rj.src[2] = ew2 + 2 * 16384; rj.dst[2] = S + OFF_RE2A; rj.n[2] = 16384;
        rj.src[3] = ew2 + 3 * 16384; rj.dst[3] = S + OFF_RE2B; rj.n[3] = 16384;
        rj.src[4] = Wg;              rj.dst[4] = S + OFF_RWG;  rj.n[4] = 32768;
        rj.src[5] = Wu;              rj.dst[5] = S + OFF_RWU;  rj.n[5] = 32768;
        rj.src[6] = W_out;           rj.dst[6] = S + OFF_RWOUT; rj.n[6] = 16384;
        rj.src[7] = node_feature;    rj.dst[7] = S + OFF_RNF;  rj.n[7] = 1048576;
        rj.src[8] = W_node;          rj.dst[8] = S + OFF_RWN;  rj.n[8] = 4096;
        k_roundW<<<dim3(4096, 9), 256>>>(rj);
    }

    k_build<<<4096, 256>>>(e_dis, e_od, ADJa, CNTIa, ADJb, CNTIb);
    k_hnum<<<32, 256>>>(numerical, W_num0, b_num0, W_num1, b_num1, HNUM);
    k_fuseW2<<<dim3(3, 9), 128>>>(Wq1, bq1, Wk1, bk1, Wv1, bv1, W_in, b_in, S);

    // node embed as tensor-core GEMM with tanh+pos epilogue
    {
        Jobs j = {};
        j.X[0] = S + OFF_RNF; j.W[0] = S + OFF_RWN; j.B[0] = b_node;
        j.Y[0] = H; j.POS[0] = pos_enc;
        gemm_tc<<<dim3(256, 1), 256, GEMM_SMEM_BYTES>>>(j, 32, BIG, 0, nullptr, 128, 32, 0);
    }

    // edge-MLP layer 1 (only surviving L_GCN iteration), both passes batched
    {
        Jobs j = {};
        j.X[0] = H;   j.W[0] = S + OFF_RE1A; j.B[0] = eb1 + 2 * 128; j.Y[0] = T0a;
        j.X[1] = H;   j.W[1] = S + OFF_RE2A; j.B[1] = eb2 + 2 * 128; j.Y[1] = T0b;
        gemm_tc<<<dim3(256, 2), 256, GEMM_SMEM_BYTES>>>(j, 128, BIG, 0, nullptr, 128, 128, 3);
    }
    {
        Jobs j = {};
        j.X[0] = T0a; j.W[0] = S + OFF_RE1B; j.B[0] = eb1 + 3 * 128; j.Y[0] = Ma;
        j.X[1] = T0b; j.W[1] = S + OFF_RE2B; j.B[1] = eb2 + 3 * 128; j.Y[1] = Mb;
        gemm_tc<<<dim3(256, 2), 256, GEMM_SMEM_BYTES>>>(j, 128, BIG, 0, nullptr, 128, 128, 1);
    }

    // gather: AVG = cvtf(sum(m[nbr]) / (cnt + eps))
    k_gather<<<8192, 256>>>(ADJa, CNTIa, ADJb, CNTIb, Ma, Mb, AVGa, AVGb);

    // gate/update GEMMs, comb fused (K=256: k<128 from H, k>=128 from AVG)
    {
        Jobs j = {};
        j.X[0] = H; j.W[0] = S + OFF_RWG; j.B[0] = bg; j.Y[0] = GTa; j.SUM[0] = AVGa;
        j.X[1] = H; j.W[1] = S + OFF_RWU; j.B[1] = bu; j.Y[1] = UTa; j.SUM[1] = AVGa;
        j.X[2] = H; j.W[2] = S + OFF_RWG; j.B[2] = bg; j.Y[2] = GTb; j.SUM[2] = AVGb;
        j.X[3] = H; j.W[3] = S + OFF_RWU; j.B[3] = bu; j.Y[3] = UTb; j.SUM[3] = AVGb;
        gemm_tc<<<dim3(256, 4), 256, GEMM_SMEM_BYTES>>>(j, 128, BIG, 0, nullptr, 128, 256, 1);
    }
    k_gcomb<<<8192, 256>>>(GTa, UTa, GTb, UTb, H, HC);

    {
        Jobs j = {};
        j.X[0] = HC; j.W[0] = S + OFF_WQF; j.B[0] = S + OFF_BQF; j.Y[0] = Q2;
        gemm_tc<<<dim3(256, 1), 256, GEMM_SMEM_BYTES>>>(j, 256, BIG, 0, nullptr, 128, 256, 0);
    }
    {
        Jobs j = {};
        j.X[0] = HC; j.W[0] = S + OFF_WKF; j.B[0] = S + OFF_BKF; j.Y[0] = K2;
        j.X[1] = HC; j.W[1] = S + OFF_WVF; j.B[1] = S + OFF_BVF; j.Y[1] = V2;
        gemm_tc<<<dim3(64, 2), 256, GEMM_SMEM_BYTES>>>(j, 256, 256, 262144, build_idx, 128, 256, 0);
    }
    k_attn<<<dim3(8, 32), 256>>>(Q2, K2, V2, OH);
    {
        Jobs j = {};
        j.X[0] = OH; j.W[0] = S + OFF_RWOUT; j.B[0] = b_out; j.Y[0] = out;
        gemm_tc<<<dim3(256, 1), 256, GEMM_SMEM_BYTES>>>(j, 128, BIG, 0, nullptr, 128, 128, 0);
    }
    k_fpart<<<dim3(32, 8), 128>>>(out, PART);
    k_final2<<<32, 256>>>(HNUM, PART, stage, out);
}